// round 7
// baseline (speedup 1.0000x reference)
#include <cuda_runtime.h>
#include <cstdint>

// ---------------- problem constants ----------------
#define BB 16
#define NN 1024
#define LL 7
#define DD 512
#define HH 8
#define HD 64
#define BND (BB * NN * DD)   // 8,388,608 floats

// ---------------- scratch (device globals; no allocations allowed) ----------
__device__ float g_agg[BND];   // lagged aggregation, later reused for O-proj
__device__ float g_Q[BND];
__device__ float g_K[BND];
__device__ float g_V[BND];
__device__ float g_att[BND];

// ---------------- packed fp32x2 helpers (FFMA2 path) ------------------------
__device__ __forceinline__ unsigned long long f32x2_dup(float x) {
    unsigned long long r; unsigned int xu = __float_as_uint(x);
    asm("mov.b64 %0, {%1, %1};" : "=l"(r) : "r"(xu));
    return r;
}
__device__ __forceinline__ unsigned long long f32x2_pack(float lo, float hi) {
    unsigned long long r;
    unsigned int a = __float_as_uint(lo), b = __float_as_uint(hi);
    asm("mov.b64 %0, {%1, %2};" : "=l"(r) : "r"(a), "r"(b));
    return r;
}
__device__ __forceinline__ void f32x2_unpack(unsigned long long v, float& lo, float& hi) {
    unsigned int a, b;
    asm("mov.b64 {%0, %1}, %2;" : "=r"(a), "=r"(b) : "l"(v));
    lo = __uint_as_float(a); hi = __uint_as_float(b);
}
__device__ __forceinline__ unsigned long long f32x2_fma(unsigned long long a,
                                                        unsigned long long b,
                                                        unsigned long long c) {
    unsigned long long d;
    asm("fma.rn.f32x2 %0, %1, %2, %3;" : "=l"(d) : "l"(a), "l"(b), "l"(c));
    return d;
}
__device__ __forceinline__ unsigned long long f32x2_mul(unsigned long long a,
                                                        unsigned long long b) {
    unsigned long long d;
    asm("mul.rn.f32x2 %0, %1, %2;" : "=l"(d) : "l"(a), "l"(b));
    return d;
}

// ---------------- kernel 1: lag softmax + weighted aggregation --------------
// out[b,n,d] = sum_l lf[b,n,l,d] * softmax(lw)[l]
__global__ void __launch_bounds__(256) lag_agg_kernel(
    const float* __restrict__ lf, const float* __restrict__ lw,
    float* __restrict__ outp)
{
    int idx = blockIdx.x * 256 + threadIdx.x;          // one float4 per thread
    // softmax of the 7 lag weights (tiny, recomputed per thread; L1-cached)
    float w[LL]; float mx = -1e30f, sum = 0.f;
#pragma unroll
    for (int l = 0; l < LL; l++) { w[l] = __ldg(&lw[l]); mx = fmaxf(mx, w[l]); }
#pragma unroll
    for (int l = 0; l < LL; l++) { w[l] = __expf(w[l] - mx); sum += w[l]; }
    float inv = 1.f / sum;

    int row = idx >> 7;                 // (b*N + n), 128 float4 per row
    int c4  = (idx & 127) << 2;
    size_t base = (size_t)row * LL * DD + c4;
    float ax = 0.f, ay = 0.f, az = 0.f, aw = 0.f;
#pragma unroll
    for (int l = 0; l < LL; l++) {
        float4 v = *reinterpret_cast<const float4*>(&lf[base + (size_t)l * DD]);
        float wl = w[l] * inv;
        ax += wl * v.x; ay += wl * v.y; az += wl * v.z; aw += wl * v.w;
    }
    float4 o = {ax, ay, az, aw};
    *reinterpret_cast<float4*>(&outp[(size_t)row * DD + c4]) = o;
}

// ---------------- kernel 2: generic NT GEMM + bias --------------------------
// C[m, o] = sum_k A[m,k] * W[o,k] + bias[o]       (torch Linear)
// M = 16384, N = K = 512.  128x128x8 tiles, 256 threads, 8x8 per thread,
// inner loop in packed f32x2 (FFMA2).
__global__ void __launch_bounds__(256) gemm_nt_bias_kernel(
    const float* __restrict__ A, const float* __restrict__ W,
    const float* __restrict__ bias, float* __restrict__ C)
{
    __shared__ __align__(16) float As[8][128];
    __shared__ __align__(16) float Ws[8][128];

    const int t    = threadIdx.x;
    const int bm   = blockIdx.y * 128;
    const int bn   = blockIdx.x * 128;
    const int ty   = t >> 4;            // 0..15
    const int tx   = t & 15;            // 0..15
    const int lrow = t >> 1;            // 0..127
    const int lseg = (t & 1) << 2;      // 0 or 4

    const float* Ag = A + (size_t)(bm + lrow) * DD + lseg;
    const float* Wg = W + (size_t)(bn + lrow) * DD + lseg;

    unsigned long long acc[8][4];
#pragma unroll
    for (int i = 0; i < 8; i++)
#pragma unroll
        for (int j = 0; j < 4; j++) acc[i][j] = 0ull;

    for (int k0 = 0; k0 < DD; k0 += 8) {
        float4 av = *reinterpret_cast<const float4*>(Ag + k0);
        float4 wv = *reinterpret_cast<const float4*>(Wg + k0);
        __syncthreads();   // previous iteration's reads complete
        As[lseg + 0][lrow] = av.x; As[lseg + 1][lrow] = av.y;
        As[lseg + 2][lrow] = av.z; As[lseg + 3][lrow] = av.w;
        Ws[lseg + 0][lrow] = wv.x; Ws[lseg + 1][lrow] = wv.y;
        Ws[lseg + 2][lrow] = wv.z; Ws[lseg + 3][lrow] = wv.w;
        __syncthreads();
#pragma unroll
        for (int kk = 0; kk < 8; kk++) {
            float4 a0 = *reinterpret_cast<const float4*>(&As[kk][ty * 8]);
            float4 a1 = *reinterpret_cast<const float4*>(&As[kk][ty * 8 + 4]);
            float4 b0 = *reinterpret_cast<const float4*>(&Ws[kk][tx * 8]);
            float4 b1 = *reinterpret_cast<const float4*>(&Ws[kk][tx * 8 + 4]);
            unsigned long long b2[4] = {
                f32x2_pack(b0.x, b0.y), f32x2_pack(b0.z, b0.w),
                f32x2_pack(b1.x, b1.y), f32x2_pack(b1.z, b1.w)
            };
            float aa[8] = {a0.x, a0.y, a0.z, a0.w, a1.x, a1.y, a1.z, a1.w};
#pragma unroll
            for (int i = 0; i < 8; i++) {
                unsigned long long ad = f32x2_dup(aa[i]);
#pragma unroll
                for (int j = 0; j < 4; j++)
                    acc[i][j] = f32x2_fma(ad, b2[j], acc[i][j]);
            }
        }
    }

    float bvals[8];
#pragma unroll
    for (int j = 0; j < 8; j++) bvals[j] = bias[bn + tx * 8 + j];
#pragma unroll
    for (int i = 0; i < 8; i++) {
        float o[8];
#pragma unroll
        for (int j = 0; j < 4; j++) {
            float lo, hi; f32x2_unpack(acc[i][j], lo, hi);
            o[2 * j]     = lo + bvals[2 * j];
            o[2 * j + 1] = hi + bvals[2 * j + 1];
        }
        float4 v0 = {o[0], o[1], o[2], o[3]};
        float4 v1 = {o[4], o[5], o[6], o[7]};
        float* Cp = C + (size_t)(bm + ty * 8 + i) * DD + bn + tx * 8;
        *reinterpret_cast<float4*>(Cp)     = v0;
        *reinterpret_cast<float4*>(Cp + 4) = v1;
    }
}

// ---------------- kernel 3: flash attention with adjacency bias -------------
// One block = one (b, h) and 64 query rows. 256 threads (16x16), each owns a
// 4x4 tile of the 64x64 score tile and a 4(rows)x4(dims) O accumulator.
// Smem: Qt (transposed+swizzled), KP (K transposed then reused for P^T), V.
__global__ void __launch_bounds__(256) attn_kernel(
    const float* __restrict__ Q, const float* __restrict__ K,
    const float* __restrict__ V, const float* __restrict__ adj,
    float* __restrict__ O)
{
    __shared__ __align__(16) float Qs[64][64];
    __shared__ __align__(16) float KP[64][64];
    __shared__ __align__(16) float Vs[64][64];

    const int t  = threadIdx.x;
    const int ty = t >> 4;          // 0..15 -> query rows 4*ty..
    const int tx = t & 15;          // 0..15 -> key cols / dims 4*tx..
    const int b  = blockIdx.y >> 3;
    const int h  = blockIdx.y & 7;
    const int n0 = blockIdx.x * 64;
    const size_t rowQ0 = (size_t)b * NN + n0;

    // ---- load Q tile, transposed + swizzled, pre-scaled by 1/sqrt(HD) ----
    {
        const int r  = t >> 4;
        const int cs = (t & 15) << 2;
#pragma unroll
        for (int it = 0; it < 4; it++) {
            int rr = r + it * 16;
            float4 v = *reinterpret_cast<const float4*>(
                &Q[(rowQ0 + rr) * DD + h * HD + cs]);
            float vv[4] = {v.x, v.y, v.z, v.w};
#pragma unroll
            for (int e = 0; e < 4; e++) {
                int d = cs + e;
                Qs[d][rr ^ ((d >> 2) << 2)] = vv[e] * 0.125f;
            }
        }
    }

    unsigned long long o2[4][2];
    float m_i[4], l_i[4];
#pragma unroll
    for (int i = 0; i < 4; i++) {
        o2[i][0] = 0ull; o2[i][1] = 0ull;
        m_i[i] = -1e30f; l_i[i] = 0.f;
    }

    const unsigned long long HALF2 = 0x3F0000003F000000ULL; // {0.5f, 0.5f}

    for (int kt = 0; kt < 16; kt++) {
        __syncthreads();    // previous PV reads / Q writes complete
        // ---- load K (transposed+swizzled) and V (row-major) tiles ----
        {
            const int r  = t >> 4;
            const int cs = (t & 15) << 2;
            const size_t rowK0 = (size_t)b * NN + kt * 64;
#pragma unroll
            for (int it = 0; it < 4; it++) {
                int rr = r + it * 16;
                float4 kv = *reinterpret_cast<const float4*>(
                    &K[(rowK0 + rr) * DD + h * HD + cs]);
                float4 vv = *reinterpret_cast<const float4*>(
                    &V[(rowK0 + rr) * DD + h * HD + cs]);
                float ka[4] = {kv.x, kv.y, kv.z, kv.w};
#pragma unroll
                for (int e = 0; e < 4; e++) {
                    int d = cs + e;
                    KP[d][rr ^ ((d >> 2) << 2)] = ka[e];
                }
                *reinterpret_cast<float4*>(&Vs[rr][cs]) = vv;
            }
        }
        __syncthreads();

        // ---- S = (Q/8) . K^T  (packed over key-column pairs) ----
        unsigned long long s2[4][2];
#pragma unroll
        for (int i = 0; i < 4; i++) { s2[i][0] = 0ull; s2[i][1] = 0ull; }
#pragma unroll 4
        for (int d = 0; d < 64; d++) {
            int sw = (d >> 2) << 2;
            float4 q4 = *reinterpret_cast<const float4*>(&Qs[d][(ty << 2) ^ sw]);
            float4 k4 = *reinterpret_cast<const float4*>(&KP[d][(tx << 2) ^ sw]);
            unsigned long long kb0 = f32x2_pack(k4.x, k4.y);
            unsigned long long kb1 = f32x2_pack(k4.z, k4.w);
            float qa[4] = {q4.x, q4.y, q4.z, q4.w};
#pragma unroll
            for (int i = 0; i < 4; i++) {
                unsigned long long qd = f32x2_dup(qa[i]);
                s2[i][0] = f32x2_fma(qd, kb0, s2[i][0]);
                s2[i][1] = f32x2_fma(qd, kb1, s2[i][1]);
            }
        }

        // ---- add 0.5 * adj_prior bias (packed float2 global loads) ----
#pragma unroll
        for (int i = 0; i < 4; i++) {
            size_t arow = (size_t)(n0 + ty * 4 + i) * NN + kt * 64 + tx * 4;
#pragma unroll
            for (int j = 0; j < 2; j++) {
                unsigned long long a2 = *reinterpret_cast<const unsigned long long*>(
                    &adj[arow + 2 * j]);
                s2[i][j] = f32x2_fma(a2, HALF2, s2[i][j]);
            }
        }

        float s[4][4];
#pragma unroll
        for (int i = 0; i < 4; i++) {
            f32x2_unpack(s2[i][0], s[i][0], s[i][1]);
            f32x2_unpack(s2[i][1], s[i][2], s[i][3]);
        }

        // ---- online softmax (row reductions over the 16 tx lanes) ----
        float p[4][4];
#pragma unroll
        for (int i = 0; i < 4; i++) {
            float rm = fmaxf(fmaxf(s[i][0], s[i][1]), fmaxf(s[i][2], s[i][3]));
            rm = fmaxf(rm, __shfl_xor_sync(0xffffffffu, rm, 1));
            rm = fmaxf(rm, __shfl_xor_sync(0xffffffffu, rm, 2));
            rm = fmaxf(rm, __shfl_xor_sync(0xffffffffu, rm, 4));
            rm = fmaxf(rm, __shfl_xor_sync(0xffffffffu, rm, 8));
            float mn    = fmaxf(m_i[i], rm);
            float alpha = __expf(m_i[i] - mn);
            m_i[i] = mn;
            float rs = 0.f;
#pragma unroll
            for (int jj = 0; jj < 4; jj++) {
                p[i][jj] = __expf(s[i][jj] - mn);
                rs += p[i][jj];
            }
            rs += __shfl_xor_sync(0xffffffffu, rs, 1);
            rs += __shfl_xor_sync(0xffffffffu, rs, 2);
            rs += __shfl_xor_sync(0xffffffffu, rs, 4);
            rs += __shfl_xor_sync(0xffffffffu, rs, 8);
            l_i[i] = l_i[i] * alpha + rs;
            unsigned long long ad = f32x2_dup(alpha);
            o2[i][0] = f32x2_mul(o2[i][0], ad);
            o2[i][1] = f32x2_mul(o2[i][1], ad);
        }

        __syncthreads();   // everyone done reading K tile
        // ---- store P transposed + swizzled into the K buffer ----
#pragma unroll
        for (int jj = 0; jj < 4; jj++) {
            int c = tx * 4 + jj;
#pragma unroll
            for (int i = 0; i < 4; i++)
                KP[c][(ty * 4 + i) ^ (tx << 2)] = p[i][jj];
        }
        __syncthreads();

        // ---- O += P^T-tile . V  (packed over dim pairs) ----
#pragma unroll 4
        for (int k = 0; k < 64; k++) {
            float4 p4 = *reinterpret_cast<const float4*>(
                &KP[k][(ty << 2) ^ ((k >> 2) << 2)]);
            float4 v4 = *reinterpret_cast<const float4*>(&Vs[k][tx << 2]);
            unsigned long long vb0 = f32x2_pack(v4.x, v4.y);
            unsigned long long vb1 = f32x2_pack(v4.z, v4.w);
            float pa[4] = {p4.x, p4.y, p4.z, p4.w};
#pragma unroll
            for (int i = 0; i < 4; i++) {
                unsigned long long pd = f32x2_dup(pa[i]);
                o2[i][0] = f32x2_fma(pd, vb0, o2[i][0]);
                o2[i][1] = f32x2_fma(pd, vb1, o2[i][1]);
            }
        }
    }

    // ---- epilogue: normalize and write out (b, n, h*64 + hd) ----
#pragma unroll
    for (int i = 0; i < 4; i++) {
        float inv = 1.0f / l_i[i];
        float o[4];
        f32x2_unpack(o2[i][0], o[0], o[1]);
        f32x2_unpack(o2[i][1], o[2], o[3]);
        float4 ov = {o[0] * inv, o[1] * inv, o[2] * inv, o[3] * inv};
        *reinterpret_cast<float4*>(
            &O[(rowQ0 + ty * 4 + i) * DD + h * HD + tx * 4]) = ov;
    }
}

// ---------------- kernel 4: residual + LayerNorm -----------------------------
__global__ void __launch_bounds__(256) ln_kernel(
    const float* __restrict__ cur, const float* __restrict__ proj,
    const float* __restrict__ g, const float* __restrict__ bta,
    float* __restrict__ out)
{
    const int m = blockIdx.x;
    const int t = threadIdx.x;
    const float2 c2 = *reinterpret_cast<const float2*>(&cur[(size_t)m * DD + t * 2]);
    const float2 p2 = *reinterpret_cast<const float2*>(&proj[(size_t)m * DD + t * 2]);
    float x0 = c2.x + p2.x, x1 = c2.y + p2.y;
    float s = x0 + x1;
    float q = x0 * x0 + x1 * x1;
#pragma unroll
    for (int off = 16; off; off >>= 1) {
        s += __shfl_xor_sync(0xffffffffu, s, off);
        q += __shfl_xor_sync(0xffffffffu, q, off);
    }
    __shared__ float ss[8], qq[8];
    int w = t >> 5, lane = t & 31;
    if (lane == 0) { ss[w] = s; qq[w] = q; }
    __syncthreads();
    if (w == 0) {
        float s2 = (lane < 8) ? ss[lane] : 0.f;
        float q2 = (lane < 8) ? qq[lane] : 0.f;
#pragma unroll
        for (int off = 4; off; off >>= 1) {
            s2 += __shfl_xor_sync(0xffffffffu, s2, off);
            q2 += __shfl_xor_sync(0xffffffffu, q2, off);
        }
        if (lane == 0) { ss[0] = s2; qq[0] = q2; }
    }
    __syncthreads();
    const float mu  = ss[0] * (1.f / 512.f);
    const float var = qq[0] * (1.f / 512.f) - mu * mu;
    const float r   = rsqrtf(var + 1e-5f);
    const float2 g2 = *reinterpret_cast<const float2*>(&g[t * 2]);
    const float2 b2 = *reinterpret_cast<const float2*>(&bta[t * 2]);
    float2 o;
    o.x = (x0 - mu) * r * g2.x + b2.x;
    o.y = (x1 - mu) * r * g2.y + b2.y;
    *reinterpret_cast<float2*>(&out[(size_t)m * DD + t * 2]) = o;
}

// ---------------- launcher ---------------------------------------------------
extern "C" void kernel_launch(void* const* d_in, const int* in_sizes, int n_in,
                              void* d_out, int out_size)
{
    (void)in_sizes; (void)n_in; (void)out_size;
    const float* cur = (const float*)d_in[0];
    const float* lf  = (const float*)d_in[1];
    const float* lw  = (const float*)d_in[2];
    const float* Wq  = (const float*)d_in[3];
    const float* bq  = (const float*)d_in[4];
    const float* Wk  = (const float*)d_in[5];
    const float* bk  = (const float*)d_in[6];
    const float* Wv  = (const float*)d_in[7];
    const float* bv  = (const float*)d_in[8];
    const float* Wo  = (const float*)d_in[9];
    const float* bo  = (const float*)d_in[10];
    const float* adj = (const float*)d_in[11];
    const float* lng = (const float*)d_in[12];
    const float* lnb = (const float*)d_in[13];
    float* out = (float*)d_out;

    float *agg, *Qb, *Kb, *Vb, *att;
    cudaGetSymbolAddress((void**)&agg, g_agg);
    cudaGetSymbolAddress((void**)&Qb,  g_Q);
    cudaGetSymbolAddress((void**)&Kb,  g_K);
    cudaGetSymbolAddress((void**)&Vb,  g_V);
    cudaGetSymbolAddress((void**)&att, g_att);

    // 1. lag softmax + aggregation
    lag_agg_kernel<<<BND / 4 / 256, 256>>>(lf, lw, agg);

    // 2-4. Q/K/V projections
    dim3 ggrid(DD / 128, (BB * NN) / 128);   // (4, 128)
    gemm_nt_bias_kernel<<<ggrid, 256>>>(cur, Wq, bq, Qb);
    gemm_nt_bias_kernel<<<ggrid, 256>>>(agg, Wk, bk, Kb);
    gemm_nt_bias_kernel<<<ggrid, 256>>>(agg, Wv, bv, Vb);

    // 5. attention with adjacency bias
    attn_kernel<<<dim3(NN / 64, BB * HH), 256>>>(Qb, Kb, Vb, adj, att);

    // 6. output projection (reuse agg buffer)
    gemm_nt_bias_kernel<<<ggrid, 256>>>(att, Wo, bo, agg);

    // 7. residual + layernorm
    ln_kernel<<<BB * NN, 256>>>(cur, agg, lng, lnb, out);
}

// round 10
// speedup vs baseline: 1.4032x; 1.4032x over previous
#include <cuda_runtime.h>
#include <cuda_bf16.h>
#include <cstdint>

// ---------------- problem constants ----------------
#define BB 16
#define NN 1024
#define LL 7
#define DD 512
#define HH 8
#define HD 64
#define BND (BB * NN * DD)   // 8,388,608 floats

// ---------------- scratch (device globals; no allocations allowed) ----------
__device__ float g_agg[BND];   // lagged aggregation, later reused for O-proj
__device__ float g_Q[BND];
__device__ float g_K[BND];
__device__ float g_V[BND];
__device__ float g_att[BND];
// bf16 hi/lo split buffers (activation A reused across stages; 4 weights)
__device__ __align__(16) __nv_bfloat16 g_ahi[BND];
__device__ __align__(16) __nv_bfloat16 g_alo[BND];
__device__ __align__(16) __nv_bfloat16 g_whi[4 * DD * DD];
__device__ __align__(16) __nv_bfloat16 g_wlo[4 * DD * DD];

// ---------------- helpers ----------------------------------------------------
__device__ __forceinline__ uint32_t smem_u32(const void* p) {
    uint32_t a;
    asm("{ .reg .u64 t; cvta.to.shared.u64 t, %1; cvt.u32.u64 %0, t; }"
        : "=r"(a) : "l"(p));
    return a;
}
__device__ __forceinline__ uint32_t swz128(uint32_t o) {
    return o ^ ((o >> 3) & 0x70);
}
// pack two fp32 into bf16x2: lo 16 bits = x, hi 16 bits = y
__device__ __forceinline__ uint32_t packbf(float x, float y) {
    uint32_t r;
    asm("cvt.rn.bf16x2.f32 %0, %1, %2;" : "=r"(r) : "f"(y), "f"(x));
    return r;
}
__device__ __forceinline__ void ldmat4(uint32_t* r, uint32_t addr) {
    asm volatile("ldmatrix.sync.aligned.m8n8.x4.shared.b16 {%0,%1,%2,%3}, [%4];"
                 : "=r"(r[0]), "=r"(r[1]), "=r"(r[2]), "=r"(r[3]) : "r"(addr));
}
__device__ __forceinline__ void mma_bf16(float* d, const uint32_t* a,
                                         const uint32_t* b) {
    asm volatile("mma.sync.aligned.m16n8k16.row.col.f32.bf16.bf16.f32 "
                 "{%0,%1,%2,%3}, {%4,%5,%6,%7}, {%8,%9}, {%0,%1,%2,%3};"
                 : "+f"(d[0]), "+f"(d[1]), "+f"(d[2]), "+f"(d[3])
                 : "r"(a[0]), "r"(a[1]), "r"(a[2]), "r"(a[3]),
                   "r"(b[0]), "r"(b[1]));
}

// ---------------- packed fp32x2 helpers (FFMA2 path, attention) -------------
__device__ __forceinline__ unsigned long long f32x2_dup(float x) {
    unsigned long long r; unsigned int xu = __float_as_uint(x);
    asm("mov.b64 %0, {%1, %1};" : "=l"(r) : "r"(xu));
    return r;
}
__device__ __forceinline__ unsigned long long f32x2_pack(float lo, float hi) {
    unsigned long long r;
    unsigned int a = __float_as_uint(lo), b = __float_as_uint(hi);
    asm("mov.b64 %0, {%1, %2};" : "=l"(r) : "r"(a), "r"(b));
    return r;
}
__device__ __forceinline__ void f32x2_unpack(unsigned long long v, float& lo, float& hi) {
    unsigned int a, b;
    asm("mov.b64 {%0, %1}, %2;" : "=r"(a), "=r"(b) : "l"(v));
    lo = __uint_as_float(a); hi = __uint_as_float(b);
}
__device__ __forceinline__ unsigned long long f32x2_fma(unsigned long long a,
                                                        unsigned long long b,
                                                        unsigned long long c) {
    unsigned long long d;
    asm("fma.rn.f32x2 %0, %1, %2, %3;" : "=l"(d) : "l"(a), "l"(b), "l"(c));
    return d;
}
__device__ __forceinline__ unsigned long long f32x2_mul(unsigned long long a,
                                                        unsigned long long b) {
    unsigned long long d;
    asm("mul.rn.f32x2 %0, %1, %2;" : "=l"(d) : "l"(a), "l"(b));
    return d;
}

// ---------------- kernel 0: fp32 -> bf16 hi/lo split -------------------------
__global__ void __launch_bounds__(256) split_kernel(
    const float* __restrict__ x, __nv_bfloat16* __restrict__ hi,
    __nv_bfloat16* __restrict__ lo, int n4)
{
    int i = blockIdx.x * 256 + threadIdx.x;
    if (i >= n4) return;
    float4 v = reinterpret_cast<const float4*>(x)[i];
    uint32_t h01 = packbf(v.x, v.y);
    uint32_t h23 = packbf(v.z, v.w);
    float h0 = __uint_as_float(h01 << 16);
    float h1 = __uint_as_float(h01 & 0xFFFF0000u);
    float h2 = __uint_as_float(h23 << 16);
    float h3 = __uint_as_float(h23 & 0xFFFF0000u);
    uint32_t l01 = packbf(v.x - h0, v.y - h1);
    uint32_t l23 = packbf(v.z - h2, v.w - h3);
    reinterpret_cast<uint2*>(hi)[i] = make_uint2(h01, h23);
    reinterpret_cast<uint2*>(lo)[i] = make_uint2(l01, l23);
}

// ---------------- kernel 1: lag softmax + weighted aggregation --------------
__global__ void __launch_bounds__(256) lag_agg_kernel(
    const float* __restrict__ lf, const float* __restrict__ lw,
    float* __restrict__ outp)
{
    int idx = blockIdx.x * 256 + threadIdx.x;          // one float4 per thread
    float w[LL]; float mx = -1e30f, sum = 0.f;
#pragma unroll
    for (int l = 0; l < LL; l++) { w[l] = __ldg(&lw[l]); mx = fmaxf(mx, w[l]); }
#pragma unroll
    for (int l = 0; l < LL; l++) { w[l] = __expf(w[l] - mx); sum += w[l]; }
    float inv = 1.f / sum;

    int row = idx >> 7;                 // (b*N + n), 128 float4 per row
    int c4  = (idx & 127) << 2;
    size_t base = (size_t)row * LL * DD + c4;
    float ax = 0.f, ay = 0.f, az = 0.f, aw = 0.f;
#pragma unroll
    for (int l = 0; l < LL; l++) {
        float4 v = *reinterpret_cast<const float4*>(&lf[base + (size_t)l * DD]);
        float wl = w[l] * inv;
        ax += wl * v.x; ay += wl * v.y; az += wl * v.z; aw += wl * v.w;
    }
    float4 o = {ax, ay, az, aw};
    *reinterpret_cast<float4*>(&outp[(size_t)row * DD + c4]) = o;
}

// ============================================================================
// kernel 2: bf16x3 GEMM via ldmatrix + mma.sync (m16n8k16)
//   C[m,o] = sum_k A[m,k] * W[o,k] + bias[o]
// CTA: 128(M) x 128(N), K-chunk 64, double-buffered smem, 8 warps (4M x 2N),
// each warp owns a 32x64 tile. Accumulates Ah*Bh + Ah*Bl + Al*Bh in fp32.
// smem per buffer: AH|AL|BH|BL, 16KB each = 64KB; x2 = 128KB dynamic.
// ============================================================================
#define GM_SMEM 131072

__global__ void __launch_bounds__(256, 1) gemm_mma_kernel(
    const __nv_bfloat16* __restrict__ Ahi, const __nv_bfloat16* __restrict__ Alo,
    const __nv_bfloat16* __restrict__ Whi, const __nv_bfloat16* __restrict__ Wlo,
    const float* __restrict__ bias, float* __restrict__ C)
{
    extern __shared__ __align__(16) char smem[];
    const int t    = threadIdx.x;
    const int wid  = t >> 5;
    const int lane = t & 31;
    const int bm   = blockIdx.y * 128;
    const int bn   = blockIdx.x * 128;
    const int wm   = (wid >> 1) * 32;   // warp M offset
    const int wn   = (wid & 1) * 64;    // warp N offset
    const uint32_t sbase = smem_u32(smem);

    float acc[2][8][4];
#pragma unroll
    for (int i = 0; i < 2; i++)
#pragma unroll
        for (int j = 0; j < 8; j++)
#pragma unroll
            for (int k = 0; k < 4; k++) acc[i][j][k] = 0.f;

    uint4 ra[2][4], rb[2][4];     // ldg staging: {hi,lo} x 4 slots

    auto ldg_chunk = [&](int c) {
        const int kb = c * 64;
#pragma unroll
        for (int i = 0; i < 4; i++) {
            int slot = t + i * 256;
            int row = slot >> 3, c8 = slot & 7;
            size_t offA = (size_t)(bm + row) * DD + kb + c8 * 8;
            size_t offB = (size_t)(bn + row) * DD + kb + c8 * 8;
            ra[0][i] = *reinterpret_cast<const uint4*>(Ahi + offA);
            ra[1][i] = *reinterpret_cast<const uint4*>(Alo + offA);
            rb[0][i] = *reinterpret_cast<const uint4*>(Whi + offB);
            rb[1][i] = *reinterpret_cast<const uint4*>(Wlo + offB);
        }
    };
    auto sts_chunk = [&](int buf) {
        char* p = smem + buf * 65536;
#pragma unroll
        for (int i = 0; i < 4; i++) {
            int slot = t + i * 256;
            int row = slot >> 3, c8 = slot & 7;
            uint32_t off = swz128((uint32_t)(row * 128 + c8 * 16));
            *reinterpret_cast<uint4*>(p + off)         = ra[0][i];
            *reinterpret_cast<uint4*>(p + 16384 + off) = ra[1][i];
            *reinterpret_cast<uint4*>(p + 32768 + off) = rb[0][i];
            *reinterpret_cast<uint4*>(p + 49152 + off) = rb[1][i];
        }
    };

    ldg_chunk(0);
    sts_chunk(0);
    __syncthreads();

    // ldmatrix per-lane address components
    const int ar = lane & 15;                       // A row within m16 tile
    const int ak = (lane >> 4) * 8;                 // A k-half
    const int br = (lane & 7) + ((lane >> 4) << 3); // B n row (two n8 tiles)
    const int bk = ((lane >> 3) & 1) * 8;           // B k-half

    for (int c = 0; c < 8; c++) {
        if (c < 7) ldg_chunk(c + 1);
        const uint32_t base = sbase + (uint32_t)((c & 1) * 65536);
#pragma unroll
        for (int ks = 0; ks < 4; ks++) {
            uint32_t ah[2][4], al[2][4];
#pragma unroll
            for (int mt = 0; mt < 2; mt++) {
                uint32_t aaddr = base + swz128(
                    (uint32_t)((wm + mt * 16 + ar) * 128 + (ks * 16 + ak) * 2));
                ldmat4(ah[mt], aaddr);
                ldmat4(al[mt], aaddr + 16384);
            }
#pragma unroll
            for (int np = 0; np < 4; np++) {
                uint32_t baddr = base + 32768 + swz128(
                    (uint32_t)((wn + np * 16 + br) * 128 + (ks * 16 + bk) * 2));
                uint32_t bh[4], bl[4];
                ldmat4(bh, baddr);
                ldmat4(bl, baddr + 16384);
#pragma unroll
                for (int mt = 0; mt < 2; mt++) {
                    mma_bf16(acc[mt][2 * np],     ah[mt], bh);
                    mma_bf16(acc[mt][2 * np + 1], ah[mt], bh + 2);
                    mma_bf16(acc[mt][2 * np],     ah[mt], bl);
                    mma_bf16(acc[mt][2 * np + 1], ah[mt], bl + 2);
                    mma_bf16(acc[mt][2 * np],     al[mt], bh);
                    mma_bf16(acc[mt][2 * np + 1], al[mt], bh + 2);
                }
            }
        }
        __syncthreads();
        if (c < 7) { sts_chunk((c + 1) & 1); __syncthreads(); }
    }

    // ---- epilogue: fragment -> global with bias (float2 stores) ----
    const int r0 = lane >> 2;
    const int c0 = (lane & 3) * 2;
#pragma unroll
    for (int mt = 0; mt < 2; mt++) {
#pragma unroll
        for (int nt = 0; nt < 8; nt++) {
            int gn = bn + wn + nt * 8 + c0;
            float2 bv = *reinterpret_cast<const float2*>(bias + gn);
            int gm = bm + wm + mt * 16 + r0;
            float2 v0 = {acc[mt][nt][0] + bv.x, acc[mt][nt][1] + bv.y};
            float2 v1 = {acc[mt][nt][2] + bv.x, acc[mt][nt][3] + bv.y};
            *reinterpret_cast<float2*>(C + (size_t)gm * DD + gn)       = v0;
            *reinterpret_cast<float2*>(C + (size_t)(gm + 8) * DD + gn) = v1;
        }
    }
}

// ---------------- kernel 3: flash attention with adjacency bias -------------
__global__ void __launch_bounds__(256) attn_kernel(
    const float* __restrict__ Q, const float* __restrict__ K,
    const float* __restrict__ V, const float* __restrict__ adj,
    float* __restrict__ O)
{
    __shared__ __align__(16) float Qs[64][64];
    __shared__ __align__(16) float KP[64][64];
    __shared__ __align__(16) float Vs[64][64];

    const int t  = threadIdx.x;
    const int ty = t >> 4;          // 0..15 -> query rows 4*ty..
    const int tx = t & 15;          // 0..15 -> key cols / dims 4*tx..
    const int b  = blockIdx.y >> 3;
    const int h  = blockIdx.y & 7;
    const int n0 = blockIdx.x * 64;
    const size_t rowQ0 = (size_t)b * NN + n0;

    // ---- load Q tile, transposed + swizzled, pre-scaled by 1/sqrt(HD) ----
    {
        const int r  = t >> 4;
        const int cs = (t & 15) << 2;
#pragma unroll
        for (int it = 0; it < 4; it++) {
            int rr = r + it * 16;
            float4 v = *reinterpret_cast<const float4*>(
                &Q[(rowQ0 + rr) * DD + h * HD + cs]);
            float vv[4] = {v.x, v.y, v.z, v.w};
#pragma unroll
            for (int e = 0; e < 4; e++) {
                int d = cs + e;
                Qs[d][rr ^ ((d >> 2) << 2)] = vv[e] * 0.125f;
            }
        }
    }

    unsigned long long o2[4][2];
    float m_i[4], l_i[4];
#pragma unroll
    for (int i = 0; i < 4; i++) {
        o2[i][0] = 0ull; o2[i][1] = 0ull;
        m_i[i] = -1e30f; l_i[i] = 0.f;
    }

    const unsigned long long HALF2 = 0x3F0000003F000000ULL; // {0.5f, 0.5f}

    for (int kt = 0; kt < 16; kt++) {
        __syncthreads();    // previous PV reads / Q writes complete
        // ---- load K (transposed+swizzled) and V (row-major) tiles ----
        {
            const int r  = t >> 4;
            const int cs = (t & 15) << 2;
            const size_t rowK0 = (size_t)b * NN + kt * 64;
#pragma unroll
            for (int it = 0; it < 4; it++) {
                int rr = r + it * 16;
                float4 kv = *reinterpret_cast<const float4*>(
                    &K[(rowK0 + rr) * DD + h * HD + cs]);
                float4 vv = *reinterpret_cast<const float4*>(
                    &V[(rowK0 + rr) * DD + h * HD + cs]);
                float ka[4] = {kv.x, kv.y, kv.z, kv.w};
#pragma unroll
                for (int e = 0; e < 4; e++) {
                    int d = cs + e;
                    KP[d][rr ^ ((d >> 2) << 2)] = ka[e];
                }
                *reinterpret_cast<float4*>(&Vs[rr][cs]) = vv;
            }
        }
        __syncthreads();

        // ---- S = (Q/8) . K^T ----
        unsigned long long s2[4][2];
#pragma unroll
        for (int i = 0; i < 4; i++) { s2[i][0] = 0ull; s2[i][1] = 0ull; }
#pragma unroll 4
        for (int d = 0; d < 64; d++) {
            int sw = (d >> 2) << 2;
            float4 q4 = *reinterpret_cast<const float4*>(&Qs[d][(ty << 2) ^ sw]);
            float4 k4 = *reinterpret_cast<const float4*>(&KP[d][(tx << 2) ^ sw]);
            unsigned long long kb0 = f32x2_pack(k4.x, k4.y);
            unsigned long long kb1 = f32x2_pack(k4.z, k4.w);
            float qa[4] = {q4.x, q4.y, q4.z, q4.w};
#pragma unroll
            for (int i = 0; i < 4; i++) {
                unsigned long long qd = f32x2_dup(qa[i]);
                s2[i][0] = f32x2_fma(qd, kb0, s2[i][0]);
                s2[i][1] = f32x2_fma(qd, kb1, s2[i][1]);
            }
        }

        // ---- add 0.5 * adj_prior bias ----
#pragma unroll
        for (int i = 0; i < 4; i++) {
            size_t arow = (size_t)(n0 + ty * 4 + i) * NN + kt * 64 + tx * 4;
#pragma unroll
            for (int j = 0; j < 2; j++) {
                unsigned long long a2 = *reinterpret_cast<const unsigned long long*>(
                    &adj[arow + 2 * j]);
                s2[i][j] = f32x2_fma(a2, HALF2, s2[i][j]);
            }
        }

        float s[4][4];
#pragma unroll
        for (int i = 0; i < 4; i++) {
            f32x2_unpack(s2[i][0], s[i][0], s[i][1]);
            f32x2_unpack(s2[i][1], s[i][2], s[i][3]);
        }

        // ---- online softmax (row reductions over the 16 tx lanes) ----
        float p[4][4];
#pragma unroll
        for (int i = 0; i < 4; i++) {
            float rm = fmaxf(fmaxf(s[i][0], s[i][1]), fmaxf(s[i][2], s[i][3]));
            rm = fmaxf(rm, __shfl_xor_sync(0xffffffffu, rm, 1));
            rm = fmaxf(rm, __shfl_xor_sync(0xffffffffu, rm, 2));
            rm = fmaxf(rm, __shfl_xor_sync(0xffffffffu, rm, 4));
            rm = fmaxf(rm, __shfl_xor_sync(0xffffffffu, rm, 8));
            float mn    = fmaxf(m_i[i], rm);
            float alpha = __expf(m_i[i] - mn);
            m_i[i] = mn;
            float rs = 0.f;
#pragma unroll
            for (int jj = 0; jj < 4; jj++) {
                p[i][jj] = __expf(s[i][jj] - mn);
                rs += p[i][jj];
            }
            rs += __shfl_xor_sync(0xffffffffu, rs, 1);
            rs += __shfl_xor_sync(0xffffffffu, rs, 2);
            rs += __shfl_xor_sync(0xffffffffu, rs, 4);
            rs += __shfl_xor_sync(0xffffffffu, rs, 8);
            l_i[i] = l_i[i] * alpha + rs;
            unsigned long long ad = f32x2_dup(alpha);
            o2[i][0] = f32x2_mul(o2[i][0], ad);
            o2[i][1] = f32x2_mul(o2[i][1], ad);
        }

        __syncthreads();   // everyone done reading K tile
        // ---- store P transposed + swizzled into the K buffer ----
#pragma unroll
        for (int jj = 0; jj < 4; jj++) {
            int c = tx * 4 + jj;
#pragma unroll
            for (int i = 0; i < 4; i++)
                KP[c][(ty * 4 + i) ^ (tx << 2)] = p[i][jj];
        }
        __syncthreads();

        // ---- O += P^T-tile . V ----
#pragma unroll 4
        for (int k = 0; k < 64; k++) {
            float4 p4 = *reinterpret_cast<const float4*>(
                &KP[k][(ty << 2) ^ ((k >> 2) << 2)]);
            float4 v4 = *reinterpret_cast<const float4*>(&Vs[k][tx << 2]);
            unsigned long long vb0 = f32x2_pack(v4.x, v4.y);
            unsigned long long vb1 = f32x2_pack(v4.z, v4.w);
            float pa[4] = {p4.x, p4.y, p4.z, p4.w};
#pragma unroll
            for (int i = 0; i < 4; i++) {
                unsigned long long pd = f32x2_dup(pa[i]);
                o2[i][0] = f32x2_fma(pd, vb0, o2[i][0]);
                o2[i][1] = f32x2_fma(pd, vb1, o2[i][1]);
            }
        }
    }

    // ---- epilogue ----
#pragma unroll
    for (int i = 0; i < 4; i++) {
        float inv = 1.0f / l_i[i];
        float o[4];
        f32x2_unpack(o2[i][0], o[0], o[1]);
        f32x2_unpack(o2[i][1], o[2], o[3]);
        float4 ov = {o[0] * inv, o[1] * inv, o[2] * inv, o[3] * inv};
        *reinterpret_cast<float4*>(
            &O[(rowQ0 + ty * 4 + i) * DD + h * HD + tx * 4]) = ov;
    }
}

// ---------------- kernel 4: residual + LayerNorm -----------------------------
__global__ void __launch_bounds__(256) ln_kernel(
    const float* __restrict__ cur, const float* __restrict__ proj,
    const float* __restrict__ g, const float* __restrict__ bta,
    float* __restrict__ out)
{
    const int m = blockIdx.x;
    const int t = threadIdx.x;
    const float2 c2 = *reinterpret_cast<const float2*>(&cur[(size_t)m * DD + t * 2]);
    const float2 p2 = *reinterpret_cast<const float2*>(&proj[(size_t)m * DD + t * 2]);
    float x0 = c2.x + p2.x, x1 = c2.y + p2.y;
    float s = x0 + x1;
    float q = x0 * x0 + x1 * x1;
#pragma unroll
    for (int off = 16; off; off >>= 1) {
        s += __shfl_xor_sync(0xffffffffu, s, off);
        q += __shfl_xor_sync(0xffffffffu, q, off);
    }
    __shared__ float ss[8], qq[8];
    int w = t >> 5, lane = t & 31;
    if (lane == 0) { ss[w] = s; qq[w] = q; }
    __syncthreads();
    if (w == 0) {
        float s2 = (lane < 8) ? ss[lane] : 0.f;
        float q2 = (lane < 8) ? qq[lane] : 0.f;
#pragma unroll
        for (int off = 4; off; off >>= 1) {
            s2 += __shfl_xor_sync(0xffffffffu, s2, off);
            q2 += __shfl_xor_sync(0xffffffffu, q2, off);
        }
        if (lane == 0) { ss[0] = s2; qq[0] = q2; }
    }
    __syncthreads();
    const float mu  = ss[0] * (1.f / 512.f);
    const float var = qq[0] * (1.f / 512.f) - mu * mu;
    const float r   = rsqrtf(var + 1e-5f);
    const float2 g2 = *reinterpret_cast<const float2*>(&g[t * 2]);
    const float2 b2 = *reinterpret_cast<const float2*>(&bta[t * 2]);
    float2 o;
    o.x = (x0 - mu) * r * g2.x + b2.x;
    o.y = (x1 - mu) * r * g2.y + b2.y;
    *reinterpret_cast<float2*>(&out[(size_t)m * DD + t * 2]) = o;
}

// ---------------- launcher ---------------------------------------------------
extern "C" void kernel_launch(void* const* d_in, const int* in_sizes, int n_in,
                              void* d_out, int out_size)
{
    (void)in_sizes; (void)n_in; (void)out_size;
    const float* cur = (const float*)d_in[0];
    const float* lf  = (const float*)d_in[1];
    const float* lw  = (const float*)d_in[2];
    const float* Wq  = (const float*)d_in[3];
    const float* bq  = (const float*)d_in[4];
    const float* Wk  = (const float*)d_in[5];
    const float* bk  = (const float*)d_in[6];
    const float* Wv  = (const float*)d_in[7];
    const float* bv  = (const float*)d_in[8];
    const float* Wo  = (const float*)d_in[9];
    const float* bo  = (const float*)d_in[10];
    const float* adj = (const float*)d_in[11];
    const float* lng = (const float*)d_in[12];
    const float* lnb = (const float*)d_in[13];
    float* out = (float*)d_out;

    float *agg, *Qb, *Kb, *Vb, *att;
    __nv_bfloat16 *ahi, *alo, *whi, *wlo;
    cudaGetSymbolAddress((void**)&agg, g_agg);
    cudaGetSymbolAddress((void**)&Qb,  g_Q);
    cudaGetSymbolAddress((void**)&Kb,  g_K);
    cudaGetSymbolAddress((void**)&Vb,  g_V);
    cudaGetSymbolAddress((void**)&att, g_att);
    cudaGetSymbolAddress((void**)&ahi, g_ahi);
    cudaGetSymbolAddress((void**)&alo, g_alo);
    cudaGetSymbolAddress((void**)&whi, g_whi);
    cudaGetSymbolAddress((void**)&wlo, g_wlo);

    cudaFuncSetAttribute(gemm_mma_kernel,
                         cudaFuncAttributeMaxDynamicSharedMemorySize, GM_SMEM);

    const int WW = DD * DD;              // 262144 elems per weight matrix
    dim3 ggrid(DD / 128, (BB * NN) / 128);   // (4, 128)

    // 1. lag softmax + aggregation
    lag_agg_kernel<<<BND / 4 / 256, 256>>>(lf, lw, agg);

    // 2. split weights (once) and current features
    split_kernel<<<WW / 4 / 256, 256>>>(Wq, whi + 0 * WW, wlo + 0 * WW, WW / 4);
    split_kernel<<<WW / 4 / 256, 256>>>(Wk, whi + 1 * WW, wlo + 1 * WW, WW / 4);
    split_kernel<<<WW / 4 / 256, 256>>>(Wv, whi + 2 * WW, wlo + 2 * WW, WW / 4);
    split_kernel<<<WW / 4 / 256, 256>>>(Wo, whi + 3 * WW, wlo + 3 * WW, WW / 4);
    split_kernel<<<BND / 4 / 256, 256>>>(cur, ahi, alo, BND / 4);

    // 3. Q projection
    gemm_mma_kernel<<<ggrid, 256, GM_SMEM>>>(ahi, alo, whi + 0 * WW, wlo + 0 * WW, bq, Qb);

    // 4. K, V projections (A = lagged aggregation)
    split_kernel<<<BND / 4 / 256, 256>>>(agg, ahi, alo, BND / 4);
    gemm_mma_kernel<<<ggrid, 256, GM_SMEM>>>(ahi, alo, whi + 1 * WW, wlo + 1 * WW, bk, Kb);
    gemm_mma_kernel<<<ggrid, 256, GM_SMEM>>>(ahi, alo, whi + 2 * WW, wlo + 2 * WW, bv, Vb);

    // 5. attention with adjacency bias
    attn_kernel<<<dim3(NN / 64, BB * HH), 256>>>(Qb, Kb, Vb, adj, att);

    // 6. output projection (reuse agg buffer as destination)
    split_kernel<<<BND / 4 / 256, 256>>>(att, ahi, alo, BND / 4);
    gemm_mma_kernel<<<ggrid, 256, GM_SMEM>>>(ahi, alo, whi + 3 * WW, wlo + 3 * WW, bo, agg);

    // 7. residual + layernorm
    ln_kernel<<<BB * NN, 256>>>(cur, agg, lng, lnb, out);
}

// round 11
// speedup vs baseline: 2.4534x; 1.7484x over previous
#include <cuda_runtime.h>
#include <cuda_bf16.h>
#include <cstdint>

// ---------------- problem constants ----------------
#define BB 16
#define NN 1024
#define LL 7
#define DD 512
#define HH 8
#define HD 64
#define BND (BB * NN * DD)   // 8,388,608 elements

// ---------------- scratch (device globals; no allocations allowed) ----------
__device__ float g_att[BND];                                   // O-proj output (fp32)
__device__ __align__(16) __nv_bfloat16 g_ahi[BND], g_alo[BND]; // cur split / attn out
__device__ __align__(16) __nv_bfloat16 g_bhi[BND], g_blo[BND]; // lagged agg split
__device__ __align__(16) __nv_bfloat16 g_qhi[BND], g_qlo[BND];
__device__ __align__(16) __nv_bfloat16 g_khi[BND], g_klo[BND];
__device__ __align__(16) __nv_bfloat16 g_vhi[BND], g_vlo[BND];
__device__ __align__(16) __nv_bfloat16 g_whi[4 * DD * DD], g_wlo[4 * DD * DD];

// ---------------- helpers ----------------------------------------------------
__device__ __forceinline__ uint32_t smem_u32(const void* p) {
    uint32_t a;
    asm("{ .reg .u64 t; cvta.to.shared.u64 t, %1; cvt.u32.u64 %0, t; }"
        : "=r"(a) : "l"(p));
    return a;
}
__device__ __forceinline__ uint32_t swz128(uint32_t o) {
    return o ^ ((o >> 3) & 0x70);
}
// pack two fp32 into bf16x2: lo 16 bits = x, hi 16 bits = y
__device__ __forceinline__ uint32_t packbf(float x, float y) {
    uint32_t r;
    asm("cvt.rn.bf16x2.f32 %0, %1, %2;" : "=r"(r) : "f"(y), "f"(x));
    return r;
}
// hi/lo error-compensated bf16 split of a pair
__device__ __forceinline__ void pack_hilo(float x, float y, uint32_t& h, uint32_t& l) {
    h = packbf(x, y);
    float hx = __uint_as_float(h << 16);
    float hy = __uint_as_float(h & 0xFFFF0000u);
    l = packbf(x - hx, y - hy);
}
__device__ __forceinline__ void ldmat4(uint32_t* r, uint32_t addr) {
    asm volatile("ldmatrix.sync.aligned.m8n8.x4.shared.b16 {%0,%1,%2,%3}, [%4];"
                 : "=r"(r[0]), "=r"(r[1]), "=r"(r[2]), "=r"(r[3]) : "r"(addr));
}
__device__ __forceinline__ void ldmat4t(uint32_t* r, uint32_t addr) {
    asm volatile("ldmatrix.sync.aligned.m8n8.x4.trans.shared.b16 {%0,%1,%2,%3}, [%4];"
                 : "=r"(r[0]), "=r"(r[1]), "=r"(r[2]), "=r"(r[3]) : "r"(addr));
}
__device__ __forceinline__ void mma_bf16(float* d, const uint32_t* a,
                                         const uint32_t* b) {
    asm volatile("mma.sync.aligned.m16n8k16.row.col.f32.bf16.bf16.f32 "
                 "{%0,%1,%2,%3}, {%4,%5,%6,%7}, {%8,%9}, {%0,%1,%2,%3};"
                 : "+f"(d[0]), "+f"(d[1]), "+f"(d[2]), "+f"(d[3])
                 : "r"(a[0]), "r"(a[1]), "r"(a[2]), "r"(a[3]),
                   "r"(b[0]), "r"(b[1]));
}
__device__ __forceinline__ void cpa16(uint32_t s, const void* g) {
    asm volatile("cp.async.cg.shared.global [%0], [%1], 16;" :: "r"(s), "l"(g));
}
#define CP_COMMIT() asm volatile("cp.async.commit_group;" ::: "memory")

// ---------------- kernel 0: fp32 -> bf16 hi/lo split -------------------------
__global__ void __launch_bounds__(256) split_kernel(
    const float* __restrict__ x, __nv_bfloat16* __restrict__ hi,
    __nv_bfloat16* __restrict__ lo, int n4)
{
    int i = blockIdx.x * 256 + threadIdx.x;
    if (i >= n4) return;
    float4 v = reinterpret_cast<const float4*>(x)[i];
    uint32_t h01, l01, h23, l23;
    pack_hilo(v.x, v.y, h01, l01);
    pack_hilo(v.z, v.w, h23, l23);
    reinterpret_cast<uint2*>(hi)[i] = make_uint2(h01, h23);
    reinterpret_cast<uint2*>(lo)[i] = make_uint2(l01, l23);
}

// ---------------- kernel 1: lag softmax + aggregation -> bf16 hi/lo ---------
__global__ void __launch_bounds__(256) lag_agg_kernel(
    const float* __restrict__ lf, const float* __restrict__ lw,
    __nv_bfloat16* __restrict__ hi, __nv_bfloat16* __restrict__ lo)
{
    int idx = blockIdx.x * 256 + threadIdx.x;          // one float4 per thread
    float w[LL]; float mx = -1e30f, sum = 0.f;
#pragma unroll
    for (int l = 0; l < LL; l++) { w[l] = __ldg(&lw[l]); mx = fmaxf(mx, w[l]); }
#pragma unroll
    for (int l = 0; l < LL; l++) { w[l] = __expf(w[l] - mx); sum += w[l]; }
    float inv = 1.f / sum;

    int row = idx >> 7;                 // (b*N + n), 128 float4 per row
    int c4  = (idx & 127) << 2;
    size_t base = (size_t)row * LL * DD + c4;
    float ax = 0.f, ay = 0.f, az = 0.f, aw = 0.f;
#pragma unroll
    for (int l = 0; l < LL; l++) {
        float4 v = *reinterpret_cast<const float4*>(&lf[base + (size_t)l * DD]);
        float wl = w[l] * inv;
        ax += wl * v.x; ay += wl * v.y; az += wl * v.z; aw += wl * v.w;
    }
    uint32_t h01, l01, h23, l23;
    pack_hilo(ax, ay, h01, l01);
    pack_hilo(az, aw, h23, l23);
    reinterpret_cast<uint2*>(hi)[idx] = make_uint2(h01, h23);
    reinterpret_cast<uint2*>(lo)[idx] = make_uint2(l01, l23);
}

// ============================================================================
// kernel 2: bf16x3 GEMM via ldmatrix + mma.sync (m16n8k16)
//   C[m,o] = (sum_k A[m,k] * W[o,k] + bias[o]) * scale
// Output either fp32 (C) or bf16 hi/lo split (Chi/Clo) when Chi != nullptr.
// ============================================================================
#define GM_SMEM 131072

__global__ void __launch_bounds__(256, 1) gemm_mma_kernel(
    const __nv_bfloat16* __restrict__ Ahi, const __nv_bfloat16* __restrict__ Alo,
    const __nv_bfloat16* __restrict__ Whi, const __nv_bfloat16* __restrict__ Wlo,
    const float* __restrict__ bias, float scale,
    float* __restrict__ C,
    __nv_bfloat16* __restrict__ Chi, __nv_bfloat16* __restrict__ Clo)
{
    extern __shared__ __align__(16) char smem[];
    const int t    = threadIdx.x;
    const int wid  = t >> 5;
    const int lane = t & 31;
    const int bm   = blockIdx.y * 128;
    const int bn   = blockIdx.x * 128;
    const int wm   = (wid >> 1) * 32;   // warp M offset
    const int wn   = (wid & 1) * 64;    // warp N offset
    const uint32_t sbase = smem_u32(smem);

    float acc[2][8][4];
#pragma unroll
    for (int i = 0; i < 2; i++)
#pragma unroll
        for (int j = 0; j < 8; j++)
#pragma unroll
            for (int k = 0; k < 4; k++) acc[i][j][k] = 0.f;

    uint4 ra[2][4], rb[2][4];     // ldg staging: {hi,lo} x 4 slots

    auto ldg_chunk = [&](int c) {
        const int kb = c * 64;
#pragma unroll
        for (int i = 0; i < 4; i++) {
            int slot = t + i * 256;
            int row = slot >> 3, c8 = slot & 7;
            size_t offA = (size_t)(bm + row) * DD + kb + c8 * 8;
            size_t offB = (size_t)(bn + row) * DD + kb + c8 * 8;
            ra[0][i] = *reinterpret_cast<const uint4*>(Ahi + offA);
            ra[1][i] = *reinterpret_cast<const uint4*>(Alo + offA);
            rb[0][i] = *reinterpret_cast<const uint4*>(Whi + offB);
            rb[1][i] = *reinterpret_cast<const uint4*>(Wlo + offB);
        }
    };
    auto sts_chunk = [&](int buf) {
        char* p = smem + buf * 65536;
#pragma unroll
        for (int i = 0; i < 4; i++) {
            int slot = t + i * 256;
            int row = slot >> 3, c8 = slot & 7;
            uint32_t off = swz128((uint32_t)(row * 128 + c8 * 16));
            *reinterpret_cast<uint4*>(p + off)         = ra[0][i];
            *reinterpret_cast<uint4*>(p + 16384 + off) = ra[1][i];
            *reinterpret_cast<uint4*>(p + 32768 + off) = rb[0][i];
            *reinterpret_cast<uint4*>(p + 49152 + off) = rb[1][i];
        }
    };

    ldg_chunk(0);
    sts_chunk(0);
    __syncthreads();

    const int ar = lane & 15;
    const int ak = (lane >> 4) * 8;
    const int br = (lane & 7) + ((lane >> 4) << 3);
    const int bk = ((lane >> 3) & 1) * 8;

    for (int c = 0; c < 8; c++) {
        if (c < 7) ldg_chunk(c + 1);
        const uint32_t base = sbase + (uint32_t)((c & 1) * 65536);
#pragma unroll
        for (int ks = 0; ks < 4; ks++) {
            uint32_t ah[2][4], al[2][4];
#pragma unroll
            for (int mt = 0; mt < 2; mt++) {
                uint32_t aaddr = base + swz128(
                    (uint32_t)((wm + mt * 16 + ar) * 128 + (ks * 16 + ak) * 2));
                ldmat4(ah[mt], aaddr);
                ldmat4(al[mt], aaddr + 16384);
            }
#pragma unroll
            for (int np = 0; np < 4; np++) {
                uint32_t baddr = base + 32768 + swz128(
                    (uint32_t)((wn + np * 16 + br) * 128 + (ks * 16 + bk) * 2));
                uint32_t bh[4], bl[4];
                ldmat4(bh, baddr);
                ldmat4(bl, baddr + 16384);
#pragma unroll
                for (int mt = 0; mt < 2; mt++) {
                    mma_bf16(acc[mt][2 * np],     ah[mt], bh);
                    mma_bf16(acc[mt][2 * np + 1], ah[mt], bh + 2);
                    mma_bf16(acc[mt][2 * np],     ah[mt], bl);
                    mma_bf16(acc[mt][2 * np + 1], ah[mt], bl + 2);
                    mma_bf16(acc[mt][2 * np],     al[mt], bh);
                    mma_bf16(acc[mt][2 * np + 1], al[mt], bh + 2);
                }
            }
        }
        __syncthreads();
        if (c < 7) { sts_chunk((c + 1) & 1); __syncthreads(); }
    }

    // ---- epilogue ----
    const int r0 = lane >> 2;
    const int c0 = (lane & 3) * 2;
#pragma unroll
    for (int mt = 0; mt < 2; mt++) {
#pragma unroll
        for (int nt = 0; nt < 8; nt++) {
            int gn = bn + wn + nt * 8 + c0;
            float2 bv = *reinterpret_cast<const float2*>(bias + gn);
            int gm = bm + wm + mt * 16 + r0;
            float v0 = (acc[mt][nt][0] + bv.x) * scale;
            float v1 = (acc[mt][nt][1] + bv.y) * scale;
            float v2 = (acc[mt][nt][2] + bv.x) * scale;
            float v3 = (acc[mt][nt][3] + bv.y) * scale;
            size_t o0 = (size_t)gm * DD + gn;
            size_t o1 = (size_t)(gm + 8) * DD + gn;
            if (Chi) {
                uint32_t h, l;
                pack_hilo(v0, v1, h, l);
                *reinterpret_cast<uint32_t*>(Chi + o0) = h;
                *reinterpret_cast<uint32_t*>(Clo + o0) = l;
                pack_hilo(v2, v3, h, l);
                *reinterpret_cast<uint32_t*>(Chi + o1) = h;
                *reinterpret_cast<uint32_t*>(Clo + o1) = l;
            } else {
                *reinterpret_cast<float2*>(C + o0) = make_float2(v0, v1);
                *reinterpret_cast<float2*>(C + o1) = make_float2(v2, v3);
            }
        }
    }
}

// ============================================================================
// kernel 3: flash attention, tensor cores, bf16x3 everywhere
//   CTA = 128 query rows x one (b,h); warp owns 16 rows.
//   16 key tiles of 64, cp.async double-buffered K/V (hi/lo).
//   S = Qs*K^T (Q pre-scaled 1/8 in GEMM) + 0.5*adj; online softmax;
//   O += P*V with P,V hi/lo split. Output: bf16 hi/lo for the O-projection.
// smem: Qh 16K | Ql 16K | stage{0,1} x {Kh 8K | Kl 8K | Vh 8K | Vl 8K}
// ============================================================================
#define AT_SMEM (32768 + 2 * 32768)

__global__ void __launch_bounds__(256, 1) attn_mma_kernel(
    const __nv_bfloat16* __restrict__ Qh_, const __nv_bfloat16* __restrict__ Ql_,
    const __nv_bfloat16* __restrict__ Kh_, const __nv_bfloat16* __restrict__ Kl_,
    const __nv_bfloat16* __restrict__ Vh_, const __nv_bfloat16* __restrict__ Vl_,
    const float* __restrict__ adj,
    __nv_bfloat16* __restrict__ Ohi, __nv_bfloat16* __restrict__ Olo)
{
    extern __shared__ __align__(1024) char smem[];
    const int t    = threadIdx.x;
    const int wid  = t >> 5;
    const int lane = t & 31;
    const int b    = blockIdx.y >> 3;
    const int h    = blockIdx.y & 7;
    const int q0   = blockIdx.x * 128;
    const uint32_t sb = smem_u32(smem);
    const size_t gb = (size_t)b * NN * DD + h * HD;

    // ---- Q tiles via cp.async (group 0, together with K/V stage 0) ----
#pragma unroll
    for (int i = 0; i < 4; i++) {
        int s2 = t + i * 256;          // 1024 slots = 128 rows x 8 col-groups
        int row = s2 >> 3, c8 = s2 & 7;
        uint32_t so = swz128((uint32_t)(row * 128 + c8 * 16));
        size_t g = gb + (size_t)(q0 + row) * DD + c8 * 8;
        cpa16(sb + so,         Qh_ + g);
        cpa16(sb + 16384 + so, Ql_ + g);
    }
    auto load_kv = [&](int stg, int kt) {
        uint32_t base = sb + 32768 + (uint32_t)stg * 32768;
#pragma unroll
        for (int i = 0; i < 2; i++) {
            int s2 = t + i * 256;      // 512 slots = 64 rows x 8 col-groups
            int row = s2 >> 3, c8 = s2 & 7;
            uint32_t so = swz128((uint32_t)(row * 128 + c8 * 16));
            size_t g = gb + (size_t)(kt * 64 + row) * DD + c8 * 8;
            cpa16(base + so,         Kh_ + g);
            cpa16(base + 8192 + so,  Kl_ + g);
            cpa16(base + 16384 + so, Vh_ + g);
            cpa16(base + 24576 + so, Vl_ + g);
        }
    };
    load_kv(0, 0); CP_COMMIT();
    load_kv(1, 1); CP_COMMIT();
    asm volatile("cp.async.wait_group 1;" ::: "memory");
    __syncthreads();

    // ---- Q A-fragments (resident) ----
    const int ar  = lane & 15;
    const int ak2 = (lane >> 4) * 16;          // byte offset of k-half
    const int wrow = wid * 16;
    uint32_t qh[4][4], ql[4][4];
#pragma unroll
    for (int ks = 0; ks < 4; ks++) {
        uint32_t ao = swz128((uint32_t)((wrow + ar) * 128 + ks * 32 + ak2));
        ldmat4(qh[ks], sb + ao);
        ldmat4(ql[ks], sb + 16384 + ao);
    }

    float o[8][4];
#pragma unroll
    for (int i = 0; i < 8; i++)
#pragma unroll
        for (int j = 0; j < 4; j++) o[i][j] = 0.f;
    float m0 = -1e30f, m1 = -1e30f, l0 = 0.f, l1 = 0.f;

    const int r0 = lane >> 2;
    const int cq = (lane & 3) * 2;
    const float* ar0 = adj + (size_t)(q0 + wrow + r0) * NN + cq;
    const float* ar1 = ar0 + 8 * NN;

    const int br  = (lane & 7) + ((lane >> 4) << 3);
    const int bk2 = ((lane >> 3) & 1) * 16;    // byte offset

    for (int kt = 0; kt < 16; kt++) {
        const uint32_t kb = sb + 32768 + (uint32_t)(kt & 1) * 32768;

        // ---- S = Q . K^T  (16 rows x 64 keys), bf16x3 ----
        float s[8][4];
#pragma unroll
        for (int i = 0; i < 8; i++)
#pragma unroll
            for (int j = 0; j < 4; j++) s[i][j] = 0.f;
#pragma unroll
        for (int ks = 0; ks < 4; ks++) {
#pragma unroll
            for (int ng = 0; ng < 4; ng++) {
                uint32_t bo = swz128((uint32_t)((ng * 16 + br) * 128 + ks * 32 + bk2));
                uint32_t bh4[4], bl4[4];
                ldmat4(bh4, kb + bo);
                ldmat4(bl4, kb + 8192 + bo);
                mma_bf16(s[2 * ng],     qh[ks], bh4);
                mma_bf16(s[2 * ng + 1], qh[ks], bh4 + 2);
                mma_bf16(s[2 * ng],     qh[ks], bl4);
                mma_bf16(s[2 * ng + 1], qh[ks], bl4 + 2);
                mma_bf16(s[2 * ng],     ql[ks], bh4);
                mma_bf16(s[2 * ng + 1], ql[ks], bh4 + 2);
            }
        }

        // ---- + 0.5 * adj ----
#pragma unroll
        for (int nt = 0; nt < 8; nt++) {
            int c = kt * 64 + nt * 8;
            float2 a0 = *reinterpret_cast<const float2*>(ar0 + c);
            float2 a1 = *reinterpret_cast<const float2*>(ar1 + c);
            s[nt][0] += 0.5f * a0.x; s[nt][1] += 0.5f * a0.y;
            s[nt][2] += 0.5f * a1.x; s[nt][3] += 0.5f * a1.y;
        }

        // ---- online softmax (rows r0, r0+8; quad shfl reduction) ----
        float tm0 = -1e30f, tm1 = -1e30f;
#pragma unroll
        for (int nt = 0; nt < 8; nt++) {
            tm0 = fmaxf(tm0, fmaxf(s[nt][0], s[nt][1]));
            tm1 = fmaxf(tm1, fmaxf(s[nt][2], s[nt][3]));
        }
        tm0 = fmaxf(tm0, __shfl_xor_sync(0xffffffffu, tm0, 1));
        tm0 = fmaxf(tm0, __shfl_xor_sync(0xffffffffu, tm0, 2));
        tm1 = fmaxf(tm1, __shfl_xor_sync(0xffffffffu, tm1, 1));
        tm1 = fmaxf(tm1, __shfl_xor_sync(0xffffffffu, tm1, 2));
        float mn0 = fmaxf(m0, tm0), mn1 = fmaxf(m1, tm1);
        float al0 = __expf(m0 - mn0), al1 = __expf(m1 - mn1);
        m0 = mn0; m1 = mn1;
        float rs0 = 0.f, rs1 = 0.f;
#pragma unroll
        for (int nt = 0; nt < 8; nt++) {
            s[nt][0] = __expf(s[nt][0] - mn0);
            s[nt][1] = __expf(s[nt][1] - mn0);
            s[nt][2] = __expf(s[nt][2] - mn1);
            s[nt][3] = __expf(s[nt][3] - mn1);
            rs0 += s[nt][0] + s[nt][1];
            rs1 += s[nt][2] + s[nt][3];
        }
        rs0 += __shfl_xor_sync(0xffffffffu, rs0, 1);
        rs0 += __shfl_xor_sync(0xffffffffu, rs0, 2);
        rs1 += __shfl_xor_sync(0xffffffffu, rs1, 1);
        rs1 += __shfl_xor_sync(0xffffffffu, rs1, 2);
        l0 = l0 * al0 + rs0;
        l1 = l1 * al1 + rs1;
#pragma unroll
        for (int ot = 0; ot < 8; ot++) {
            o[ot][0] *= al0; o[ot][1] *= al0;
            o[ot][2] *= al1; o[ot][3] *= al1;
        }

        // ---- O += P . V  (P,V hi/lo; V via ldmatrix.trans) ----
#pragma unroll
        for (int k2 = 0; k2 < 4; k2++) {
            uint32_t ph[4], pl[4];
            pack_hilo(s[2 * k2][0],     s[2 * k2][1],     ph[0], pl[0]);
            pack_hilo(s[2 * k2][2],     s[2 * k2][3],     ph[1], pl[1]);
            pack_hilo(s[2 * k2 + 1][0], s[2 * k2 + 1][1], ph[2], pl[2]);
            pack_hilo(s[2 * k2 + 1][2], s[2 * k2 + 1][3], ph[3], pl[3]);
#pragma unroll
            for (int dt = 0; dt < 4; dt++) {
                uint32_t vo = swz128((uint32_t)((k2 * 16 + ar) * 128 + dt * 32 + ak2));
                uint32_t vh4[4], vl4[4];
                ldmat4t(vh4, kb + 16384 + vo);
                ldmat4t(vl4, kb + 24576 + vo);
                mma_bf16(o[2 * dt],     ph, vh4);
                mma_bf16(o[2 * dt + 1], ph, vh4 + 2);
                mma_bf16(o[2 * dt],     ph, vl4);
                mma_bf16(o[2 * dt + 1], ph, vl4 + 2);
                mma_bf16(o[2 * dt],     pl, vh4);
                mma_bf16(o[2 * dt + 1], pl, vh4 + 2);
            }
        }

        // ---- pipeline bookkeeping ----
        __syncthreads();                         // all warps done with stage kt&1
        if (kt + 2 < 16) { load_kv(kt & 1, kt + 2); CP_COMMIT(); }
        if (kt + 1 < 16) {
            if (kt + 2 < 16)
                asm volatile("cp.async.wait_group 1;" ::: "memory");
            else
                asm volatile("cp.async.wait_group 0;" ::: "memory");
            __syncthreads();
        }
    }

    // ---- epilogue: normalize, split to hi/lo bf16 ----
    float i0 = 1.f / l0, i1 = 1.f / l1;
    size_t ob0 = gb + (size_t)(q0 + wrow + r0) * DD;
    size_t ob1 = ob0 + 8 * DD;
#pragma unroll
    for (int dt = 0; dt < 8; dt++) {
        int dcol = dt * 8 + cq;
        uint32_t h0, lo0, h1, lo1;
        pack_hilo(o[dt][0] * i0, o[dt][1] * i0, h0, lo0);
        pack_hilo(o[dt][2] * i1, o[dt][3] * i1, h1, lo1);
        *reinterpret_cast<uint32_t*>(Ohi + ob0 + dcol) = h0;
        *reinterpret_cast<uint32_t*>(Olo + ob0 + dcol) = lo0;
        *reinterpret_cast<uint32_t*>(Ohi + ob1 + dcol) = h1;
        *reinterpret_cast<uint32_t*>(Olo + ob1 + dcol) = lo1;
    }
}

// ---------------- kernel 4: residual + LayerNorm -----------------------------
__global__ void __launch_bounds__(256) ln_kernel(
    const float* __restrict__ cur, const float* __restrict__ proj,
    const float* __restrict__ g, const float* __restrict__ bta,
    float* __restrict__ out)
{
    const int m = blockIdx.x;
    const int t = threadIdx.x;
    const float2 c2 = *reinterpret_cast<const float2*>(&cur[(size_t)m * DD + t * 2]);
    const float2 p2 = *reinterpret_cast<const float2*>(&proj[(size_t)m * DD + t * 2]);
    float x0 = c2.x + p2.x, x1 = c2.y + p2.y;
    float s = x0 + x1;
    float q = x0 * x0 + x1 * x1;
#pragma unroll
    for (int off = 16; off; off >>= 1) {
        s += __shfl_xor_sync(0xffffffffu, s, off);
        q += __shfl_xor_sync(0xffffffffu, q, off);
    }
    __shared__ float ss[8], qq[8];
    int w = t >> 5, lane = t & 31;
    if (lane == 0) { ss[w] = s; qq[w] = q; }
    __syncthreads();
    if (w == 0) {
        float s2 = (lane < 8) ? ss[lane] : 0.f;
        float q2 = (lane < 8) ? qq[lane] : 0.f;
#pragma unroll
        for (int off = 4; off; off >>= 1) {
            s2 += __shfl_xor_sync(0xffffffffu, s2, off);
            q2 += __shfl_xor_sync(0xffffffffu, q2, off);
        }
        if (lane == 0) { ss[0] = s2; qq[0] = q2; }
    }
    __syncthreads();
    const float mu  = ss[0] * (1.f / 512.f);
    const float var = qq[0] * (1.f / 512.f) - mu * mu;
    const float r   = rsqrtf(var + 1e-5f);
    const float2 g2 = *reinterpret_cast<const float2*>(&g[t * 2]);
    const float2 b2 = *reinterpret_cast<const float2*>(&bta[t * 2]);
    float2 o;
    o.x = (x0 - mu) * r * g2.x + b2.x;
    o.y = (x1 - mu) * r * g2.y + b2.y;
    *reinterpret_cast<float2*>(&out[(size_t)m * DD + t * 2]) = o;
}

// ---------------- launcher ---------------------------------------------------
extern "C" void kernel_launch(void* const* d_in, const int* in_sizes, int n_in,
                              void* d_out, int out_size)
{
    (void)in_sizes; (void)n_in; (void)out_size;
    const float* cur = (const float*)d_in[0];
    const float* lf  = (const float*)d_in[1];
    const float* lw  = (const float*)d_in[2];
    const float* Wq  = (const float*)d_in[3];
    const float* bq  = (const float*)d_in[4];
    const float* Wk  = (const float*)d_in[5];
    const float* bk  = (const float*)d_in[6];
    const float* Wv  = (const float*)d_in[7];
    const float* bv  = (const float*)d_in[8];
    const float* Wo  = (const float*)d_in[9];
    const float* bo  = (const float*)d_in[10];
    const float* adj = (const float*)d_in[11];
    const float* lng = (const float*)d_in[12];
    const float* lnb = (const float*)d_in[13];
    float* out = (float*)d_out;

    float* att;
    __nv_bfloat16 *ahi, *alo, *bhi, *blo, *whi, *wlo;
    __nv_bfloat16 *qhi, *qlo, *khi, *klo, *vhi, *vlo;
    cudaGetSymbolAddress((void**)&att, g_att);
    cudaGetSymbolAddress((void**)&ahi, g_ahi);
    cudaGetSymbolAddress((void**)&alo, g_alo);
    cudaGetSymbolAddress((void**)&bhi, g_bhi);
    cudaGetSymbolAddress((void**)&blo, g_blo);
    cudaGetSymbolAddress((void**)&whi, g_whi);
    cudaGetSymbolAddress((void**)&wlo, g_wlo);
    cudaGetSymbolAddress((void**)&qhi, g_qhi);
    cudaGetSymbolAddress((void**)&qlo, g_qlo);
    cudaGetSymbolAddress((void**)&khi, g_khi);
    cudaGetSymbolAddress((void**)&klo, g_klo);
    cudaGetSymbolAddress((void**)&vhi, g_vhi);
    cudaGetSymbolAddress((void**)&vlo, g_vlo);

    cudaFuncSetAttribute(gemm_mma_kernel,
                         cudaFuncAttributeMaxDynamicSharedMemorySize, GM_SMEM);
    cudaFuncSetAttribute(attn_mma_kernel,
                         cudaFuncAttributeMaxDynamicSharedMemorySize, AT_SMEM);

    const int WW = DD * DD;                  // 262144 elems per weight matrix
    dim3 ggrid(DD / 128, (BB * NN) / 128);   // (4, 128)

    // 1. input splits (weights once, current features)
    split_kernel<<<WW / 4 / 256, 256>>>(Wq, whi + 0 * WW, wlo + 0 * WW, WW / 4);
    split_kernel<<<WW / 4 / 256, 256>>>(Wk, whi + 1 * WW, wlo + 1 * WW, WW / 4);
    split_kernel<<<WW / 4 / 256, 256>>>(Wv, whi + 2 * WW, wlo + 2 * WW, WW / 4);
    split_kernel<<<WW / 4 / 256, 256>>>(Wo, whi + 3 * WW, wlo + 3 * WW, WW / 4);
    split_kernel<<<BND / 4 / 256, 256>>>(cur, ahi, alo, BND / 4);

    // 2. lag softmax + aggregation -> bf16 hi/lo directly
    lag_agg_kernel<<<BND / 4 / 256, 256>>>(lf, lw, bhi, blo);

    // 3. projections (Q pre-scaled by 1/sqrt(HD) = 0.125)
    gemm_mma_kernel<<<ggrid, 256, GM_SMEM>>>(ahi, alo, whi + 0 * WW, wlo + 0 * WW,
                                             bq, 0.125f, nullptr, qhi, qlo);
    gemm_mma_kernel<<<ggrid, 256, GM_SMEM>>>(bhi, blo, whi + 1 * WW, wlo + 1 * WW,
                                             bk, 1.0f, nullptr, khi, klo);
    gemm_mma_kernel<<<ggrid, 256, GM_SMEM>>>(bhi, blo, whi + 2 * WW, wlo + 2 * WW,
                                             bv, 1.0f, nullptr, vhi, vlo);

    // 4. attention (tensor cores) -> hi/lo split for O-projection
    attn_mma_kernel<<<dim3(NN / 128, BB * HH), 256, AT_SMEM>>>(
        qhi, qlo, khi, klo, vhi, vlo, adj, ahi, alo);

    // 5. output projection -> fp32
    gemm_mma_kernel<<<ggrid, 256, GM_SMEM>>>(ahi, alo, whi + 3 * WW, wlo + 3 * WW,
                                             bo, 1.0f, att, nullptr, nullptr);

    // 6. residual + layernorm
    ln_kernel<<<BB * NN, 256>>>(cur, att, lng, lnb, out);
}

// round 12
// speedup vs baseline: 2.6559x; 1.0826x over previous
#include <cuda_runtime.h>
#include <cuda_bf16.h>
#include <cstdint>

// ---------------- problem constants ----------------
#define BB 16
#define NN 1024
#define LL 7
#define DD 512
#define HH 8
#define HD 64
#define BND (BB * NN * DD)   // 8,388,608 elements

// ---------------- scratch (device globals; no allocations allowed) ----------
__device__ float g_att[BND];                                   // O-proj output (fp32)
__device__ __align__(16) __nv_bfloat16 g_ahi[BND], g_alo[BND]; // cur split / attn out
__device__ __align__(16) __nv_bfloat16 g_bhi[BND], g_blo[BND]; // lagged agg split
__device__ __align__(16) __nv_bfloat16 g_qhi[BND], g_qlo[BND];
__device__ __align__(16) __nv_bfloat16 g_khi[BND], g_klo[BND];
__device__ __align__(16) __nv_bfloat16 g_vhi[BND], g_vlo[BND];
__device__ __align__(16) __nv_bfloat16 g_whi[4 * DD * DD], g_wlo[4 * DD * DD];

// ---------------- helpers ----------------------------------------------------
__device__ __forceinline__ uint32_t smem_u32(const void* p) {
    uint32_t a;
    asm("{ .reg .u64 t; cvta.to.shared.u64 t, %1; cvt.u32.u64 %0, t; }"
        : "=r"(a) : "l"(p));
    return a;
}
__device__ __forceinline__ uint32_t swz128(uint32_t o) {
    return o ^ ((o >> 3) & 0x70);
}
// pack two fp32 into bf16x2: lo 16 bits = x, hi 16 bits = y
__device__ __forceinline__ uint32_t packbf(float x, float y) {
    uint32_t r;
    asm("cvt.rn.bf16x2.f32 %0, %1, %2;" : "=r"(r) : "f"(y), "f"(x));
    return r;
}
// hi/lo error-compensated bf16 split of a pair
__device__ __forceinline__ void pack_hilo(float x, float y, uint32_t& h, uint32_t& l) {
    h = packbf(x, y);
    float hx = __uint_as_float(h << 16);
    float hy = __uint_as_float(h & 0xFFFF0000u);
    l = packbf(x - hx, y - hy);
}
__device__ __forceinline__ void ldmat4(uint32_t* r, uint32_t addr) {
    asm volatile("ldmatrix.sync.aligned.m8n8.x4.shared.b16 {%0,%1,%2,%3}, [%4];"
                 : "=r"(r[0]), "=r"(r[1]), "=r"(r[2]), "=r"(r[3]) : "r"(addr));
}
__device__ __forceinline__ void ldmat4t(uint32_t* r, uint32_t addr) {
    asm volatile("ldmatrix.sync.aligned.m8n8.x4.trans.shared.b16 {%0,%1,%2,%3}, [%4];"
                 : "=r"(r[0]), "=r"(r[1]), "=r"(r[2]), "=r"(r[3]) : "r"(addr));
}
__device__ __forceinline__ void mma_bf16(float* d, const uint32_t* a,
                                         const uint32_t* b) {
    asm volatile("mma.sync.aligned.m16n8k16.row.col.f32.bf16.bf16.f32 "
                 "{%0,%1,%2,%3}, {%4,%5,%6,%7}, {%8,%9}, {%0,%1,%2,%3};"
                 : "+f"(d[0]), "+f"(d[1]), "+f"(d[2]), "+f"(d[3])
                 : "r"(a[0]), "r"(a[1]), "r"(a[2]), "r"(a[3]),
                   "r"(b[0]), "r"(b[1]));
}
__device__ __forceinline__ void cpa16(uint32_t s, const void* g) {
    asm volatile("cp.async.cg.shared.global [%0], [%1], 16;" :: "r"(s), "l"(g));
}
#define CP_COMMIT() asm volatile("cp.async.commit_group;" ::: "memory")

// ---------------- kernel 0: fp32 -> bf16 hi/lo split -------------------------
__global__ void __launch_bounds__(256) split_kernel(
    const float* __restrict__ x, __nv_bfloat16* __restrict__ hi,
    __nv_bfloat16* __restrict__ lo, int n4)
{
    int i = blockIdx.x * 256 + threadIdx.x;
    if (i >= n4) return;
    float4 v = reinterpret_cast<const float4*>(x)[i];
    uint32_t h01, l01, h23, l23;
    pack_hilo(v.x, v.y, h01, l01);
    pack_hilo(v.z, v.w, h23, l23);
    reinterpret_cast<uint2*>(hi)[i] = make_uint2(h01, h23);
    reinterpret_cast<uint2*>(lo)[i] = make_uint2(l01, l23);
}

// ---------------- kernel 1: lag softmax + aggregation -> bf16 hi/lo ---------
__global__ void __launch_bounds__(256) lag_agg_kernel(
    const float* __restrict__ lf, const float* __restrict__ lw,
    __nv_bfloat16* __restrict__ hi, __nv_bfloat16* __restrict__ lo)
{
    int idx = blockIdx.x * 256 + threadIdx.x;          // one float4 per thread
    float w[LL]; float mx = -1e30f, sum = 0.f;
#pragma unroll
    for (int l = 0; l < LL; l++) { w[l] = __ldg(&lw[l]); mx = fmaxf(mx, w[l]); }
#pragma unroll
    for (int l = 0; l < LL; l++) { w[l] = __expf(w[l] - mx); sum += w[l]; }
    float inv = 1.f / sum;

    int row = idx >> 7;                 // (b*N + n), 128 float4 per row
    int c4  = (idx & 127) << 2;
    size_t base = (size_t)row * LL * DD + c4;
    float ax = 0.f, ay = 0.f, az = 0.f, aw = 0.f;
#pragma unroll
    for (int l = 0; l < LL; l++) {
        float4 v = *reinterpret_cast<const float4*>(&lf[base + (size_t)l * DD]);
        float wl = w[l] * inv;
        ax += wl * v.x; ay += wl * v.y; az += wl * v.z; aw += wl * v.w;
    }
    uint32_t h01, l01, h23, l23;
    pack_hilo(ax, ay, h01, l01);
    pack_hilo(az, aw, h23, l23);
    reinterpret_cast<uint2*>(hi)[idx] = make_uint2(h01, h23);
    reinterpret_cast<uint2*>(lo)[idx] = make_uint2(l01, l23);
}

// ============================================================================
// kernel 2: bf16x3 GEMM via cp.async + ldmatrix + mma.sync (m16n8k16)
//   C[m,o] = (sum_k A[m,k] * W[o,k] + bias[o]) * scale
// CTA 128x128, K-chunk 32, 3-stage cp.async pipeline, 2 CTAs/SM.
// Stage layout (32KB): A 16KB | B 16KB; each row 128B = [hi 32bf16 | lo 32bf16]
// ============================================================================
#define GKC  32
#define GSTG 32768
#define GM_SMEM (3 * GSTG)     // 98304 -> 2 CTAs/SM

__global__ void __launch_bounds__(256, 2) gemm_mma_kernel(
    const __nv_bfloat16* __restrict__ Ahi, const __nv_bfloat16* __restrict__ Alo,
    const __nv_bfloat16* __restrict__ Whi, const __nv_bfloat16* __restrict__ Wlo,
    const float* __restrict__ bias, float scale,
    float* __restrict__ C,
    __nv_bfloat16* __restrict__ Chi, __nv_bfloat16* __restrict__ Clo)
{
    extern __shared__ __align__(1024) char smem[];
    const int t    = threadIdx.x;
    const int wid  = t >> 5;
    const int lane = t & 31;
    const int bm   = blockIdx.y * 128;
    const int bn   = blockIdx.x * 128;
    const int wm   = (wid >> 1) * 32;   // warp M offset
    const int wn   = (wid & 1) * 64;    // warp N offset
    const uint32_t sbase = smem_u32(smem);

    float acc[2][8][4];
#pragma unroll
    for (int i = 0; i < 2; i++)
#pragma unroll
        for (int j = 0; j < 8; j++)
#pragma unroll
            for (int k = 0; k < 4; k++) acc[i][j][k] = 0.f;

    // per-thread load geometry: 1024 slots = 128 rows x 8 x 16B (4 hi + 4 lo)
    auto load_chunk = [&](int s, int c) {
        const uint32_t base = sbase + (uint32_t)s * GSTG;
        const int kb = c * GKC;
#pragma unroll
        for (int i = 0; i < 4; i++) {
            int slot = t + i * 256;
            int row = slot >> 3, j = slot & 7;
            uint32_t dst = swz128((uint32_t)(row * 128 + j * 16));
            const __nv_bfloat16* a = (j < 4) ? Ahi : Alo;
            const __nv_bfloat16* w = (j < 4) ? Whi : Wlo;
            int jc = (j & 3) * 8;
            cpa16(base + dst,         a + (size_t)(bm + row) * DD + kb + jc);
            cpa16(base + 16384 + dst, w + (size_t)(bn + row) * DD + kb + jc);
        }
    };

    load_chunk(0, 0); CP_COMMIT();
    load_chunk(1, 1); CP_COMMIT();
    load_chunk(2, 2); CP_COMMIT();

    const int ar  = lane & 15;
    const int ak2 = (lane >> 4) * 16;               // byte offset of k-half
    const int br  = (lane & 7) + ((lane >> 4) << 3);
    const int bk2 = ((lane >> 3) & 1) * 16;

    for (int c = 0; c < 16; c++) {
        if (c < 14)      asm volatile("cp.async.wait_group 2;" ::: "memory");
        else if (c == 14) asm volatile("cp.async.wait_group 1;" ::: "memory");
        else             asm volatile("cp.async.wait_group 0;" ::: "memory");
        __syncthreads();

        const uint32_t base = sbase + (uint32_t)((c % 3) * GSTG);
#pragma unroll
        for (int ks = 0; ks < 2; ks++) {
            uint32_t ah[2][4], al[2][4];
#pragma unroll
            for (int mt = 0; mt < 2; mt++) {
                uint32_t ro = (uint32_t)((wm + mt * 16 + ar) * 128 + ks * 32 + ak2);
                ldmat4(ah[mt], base + swz128(ro));
                ldmat4(al[mt], base + swz128(ro + 64));
            }
#pragma unroll
            for (int np = 0; np < 4; np++) {
                uint32_t ro = (uint32_t)((wn + np * 16 + br) * 128 + ks * 32 + bk2);
                uint32_t bh[4], bl[4];
                ldmat4(bh, base + 16384 + swz128(ro));
                ldmat4(bl, base + 16384 + swz128(ro + 64));
#pragma unroll
                for (int mt = 0; mt < 2; mt++) {
                    mma_bf16(acc[mt][2 * np],     ah[mt], bh);
                    mma_bf16(acc[mt][2 * np + 1], ah[mt], bh + 2);
                    mma_bf16(acc[mt][2 * np],     ah[mt], bl);
                    mma_bf16(acc[mt][2 * np + 1], ah[mt], bl + 2);
                    mma_bf16(acc[mt][2 * np],     al[mt], bh);
                    mma_bf16(acc[mt][2 * np + 1], al[mt], bh + 2);
                }
            }
        }
        __syncthreads();
        if (c + 3 < 16) { load_chunk(c % 3, c + 3); CP_COMMIT(); }
    }

    // ---- epilogue ----
    const int r0 = lane >> 2;
    const int c0 = (lane & 3) * 2;
#pragma unroll
    for (int mt = 0; mt < 2; mt++) {
#pragma unroll
        for (int nt = 0; nt < 8; nt++) {
            int gn = bn + wn + nt * 8 + c0;
            float2 bv = *reinterpret_cast<const float2*>(bias + gn);
            int gm = bm + wm + mt * 16 + r0;
            float v0 = (acc[mt][nt][0] + bv.x) * scale;
            float v1 = (acc[mt][nt][1] + bv.y) * scale;
            float v2 = (acc[mt][nt][2] + bv.x) * scale;
            float v3 = (acc[mt][nt][3] + bv.y) * scale;
            size_t o0 = (size_t)gm * DD + gn;
            size_t o1 = (size_t)(gm + 8) * DD + gn;
            if (Chi) {
                uint32_t h, l;
                pack_hilo(v0, v1, h, l);
                *reinterpret_cast<uint32_t*>(Chi + o0) = h;
                *reinterpret_cast<uint32_t*>(Clo + o0) = l;
                pack_hilo(v2, v3, h, l);
                *reinterpret_cast<uint32_t*>(Chi + o1) = h;
                *reinterpret_cast<uint32_t*>(Clo + o1) = l;
            } else {
                *reinterpret_cast<float2*>(C + o0) = make_float2(v0, v1);
                *reinterpret_cast<float2*>(C + o1) = make_float2(v2, v3);
            }
        }
    }
}

// ============================================================================
// kernel 3: flash attention, tensor cores, bf16x3; 2 CTAs/SM
//   CTA = 128 query rows x one (b,h); warp owns 16 rows.
//   16 key tiles of 64, cp.async double-buffered K/V (hi/lo).
//   Q-hi fragments register-resident; Q-lo reloaded per k-step (reg relief).
// smem: Qh 16K | Ql 16K | stage{0,1} x {Kh 8K | Kl 8K | Vh 8K | Vl 8K} = 96K
// ============================================================================
#define AT_SMEM (32768 + 2 * 32768)

__global__ void __launch_bounds__(256, 2) attn_mma_kernel(
    const __nv_bfloat16* __restrict__ Qh_, const __nv_bfloat16* __restrict__ Ql_,
    const __nv_bfloat16* __restrict__ Kh_, const __nv_bfloat16* __restrict__ Kl_,
    const __nv_bfloat16* __restrict__ Vh_, const __nv_bfloat16* __restrict__ Vl_,
    const float* __restrict__ adj,
    __nv_bfloat16* __restrict__ Ohi, __nv_bfloat16* __restrict__ Olo)
{
    extern __shared__ __align__(1024) char smem[];
    const int t    = threadIdx.x;
    const int wid  = t >> 5;
    const int lane = t & 31;
    const int b    = blockIdx.y >> 3;
    const int h    = blockIdx.y & 7;
    const int q0   = blockIdx.x * 128;
    const uint32_t sb = smem_u32(smem);
    const size_t gb = (size_t)b * NN * DD + h * HD;

    // ---- Q tiles via cp.async (group 0, together with K/V stage 0) ----
#pragma unroll
    for (int i = 0; i < 4; i++) {
        int s2 = t + i * 256;          // 1024 slots = 128 rows x 8 col-groups
        int row = s2 >> 3, c8 = s2 & 7;
        uint32_t so = swz128((uint32_t)(row * 128 + c8 * 16));
        size_t g = gb + (size_t)(q0 + row) * DD + c8 * 8;
        cpa16(sb + so,         Qh_ + g);
        cpa16(sb + 16384 + so, Ql_ + g);
    }
    auto load_kv = [&](int stg, int kt) {
        uint32_t base = sb + 32768 + (uint32_t)stg * 32768;
#pragma unroll
        for (int i = 0; i < 2; i++) {
            int s2 = t + i * 256;      // 512 slots = 64 rows x 8 col-groups
            int row = s2 >> 3, c8 = s2 & 7;
            uint32_t so = swz128((uint32_t)(row * 128 + c8 * 16));
            size_t g = gb + (size_t)(kt * 64 + row) * DD + c8 * 8;
            cpa16(base + so,         Kh_ + g);
            cpa16(base + 8192 + so,  Kl_ + g);
            cpa16(base + 16384 + so, Vh_ + g);
            cpa16(base + 24576 + so, Vl_ + g);
        }
    };
    load_kv(0, 0); CP_COMMIT();
    load_kv(1, 1); CP_COMMIT();
    asm volatile("cp.async.wait_group 1;" ::: "memory");
    __syncthreads();

    // ---- Q-hi A-fragments (resident); Q-lo reloaded on demand ----
    const int ar  = lane & 15;
    const int ak2 = (lane >> 4) * 16;          // byte offset of k-half
    const int wrow = wid * 16;
    uint32_t qh[4][4], qao[4];
#pragma unroll
    for (int ks = 0; ks < 4; ks++) {
        qao[ks] = sb + swz128((uint32_t)((wrow + ar) * 128 + ks * 32 + ak2));
        ldmat4(qh[ks], qao[ks]);
    }

    float o[8][4];
#pragma unroll
    for (int i = 0; i < 8; i++)
#pragma unroll
        for (int j = 0; j < 4; j++) o[i][j] = 0.f;
    float m0 = -1e30f, m1 = -1e30f, l0 = 0.f, l1 = 0.f;

    const int r0 = lane >> 2;
    const int cq = (lane & 3) * 2;
    const float* ar0 = adj + (size_t)(q0 + wrow + r0) * NN + cq;
    const float* ar1 = ar0 + 8 * NN;

    const int br  = (lane & 7) + ((lane >> 4) << 3);
    const int bk2 = ((lane >> 3) & 1) * 16;    // byte offset

    for (int kt = 0; kt < 16; kt++) {
        const uint32_t kb = sb + 32768 + (uint32_t)(kt & 1) * 32768;

        // ---- S = Q . K^T  (16 rows x 64 keys), bf16x3 ----
        float s[8][4];
#pragma unroll
        for (int i = 0; i < 8; i++)
#pragma unroll
            for (int j = 0; j < 4; j++) s[i][j] = 0.f;
#pragma unroll
        for (int ks = 0; ks < 4; ks++) {
            uint32_t qlk[4];
            ldmat4(qlk, qao[ks] + 16384);
#pragma unroll
            for (int ng = 0; ng < 4; ng++) {
                uint32_t bo = swz128((uint32_t)((ng * 16 + br) * 128 + ks * 32 + bk2));
                uint32_t bh4[4], bl4[4];
                ldmat4(bh4, kb + bo);
                ldmat4(bl4, kb + 8192 + bo);
                mma_bf16(s[2 * ng],     qh[ks], bh4);
                mma_bf16(s[2 * ng + 1], qh[ks], bh4 + 2);
                mma_bf16(s[2 * ng],     qh[ks], bl4);
                mma_bf16(s[2 * ng + 1], qh[ks], bl4 + 2);
                mma_bf16(s[2 * ng],     qlk, bh4);
                mma_bf16(s[2 * ng + 1], qlk, bh4 + 2);
            }
        }

        // ---- + 0.5 * adj ----
#pragma unroll
        for (int nt = 0; nt < 8; nt++) {
            int c = kt * 64 + nt * 8;
            float2 a0 = *reinterpret_cast<const float2*>(ar0 + c);
            float2 a1 = *reinterpret_cast<const float2*>(ar1 + c);
            s[nt][0] += 0.5f * a0.x; s[nt][1] += 0.5f * a0.y;
            s[nt][2] += 0.5f * a1.x; s[nt][3] += 0.5f * a1.y;
        }

        // ---- online softmax (rows r0, r0+8; quad shfl reduction) ----
        float tm0 = -1e30f, tm1 = -1e30f;
#pragma unroll
        for (int nt = 0; nt < 8; nt++) {
            tm0 = fmaxf(tm0, fmaxf(s[nt][0], s[nt][1]));
            tm1 = fmaxf(tm1, fmaxf(s[nt][2], s[nt][3]));
        }
        tm0 = fmaxf(tm0, __shfl_xor_sync(0xffffffffu, tm0, 1));
        tm0 = fmaxf(tm0, __shfl_xor_sync(0xffffffffu, tm0, 2));
        tm1 = fmaxf(tm1, __shfl_xor_sync(0xffffffffu, tm1, 1));
        tm1 = fmaxf(tm1, __shfl_xor_sync(0xffffffffu, tm1, 2));
        float mn0 = fmaxf(m0, tm0), mn1 = fmaxf(m1, tm1);
        float al0 = __expf(m0 - mn0), al1 = __expf(m1 - mn1);
        m0 = mn0; m1 = mn1;
        float rs0 = 0.f, rs1 = 0.f;
#pragma unroll
        for (int nt = 0; nt < 8; nt++) {
            s[nt][0] = __expf(s[nt][0] - mn0);
            s[nt][1] = __expf(s[nt][1] - mn0);
            s[nt][2] = __expf(s[nt][2] - mn1);
            s[nt][3] = __expf(s[nt][3] - mn1);
            rs0 += s[nt][0] + s[nt][1];
            rs1 += s[nt][2] + s[nt][3];
        }
        rs0 += __shfl_xor_sync(0xffffffffu, rs0, 1);
        rs0 += __shfl_xor_sync(0xffffffffu, rs0, 2);
        rs1 += __shfl_xor_sync(0xffffffffu, rs1, 1);
        rs1 += __shfl_xor_sync(0xffffffffu, rs1, 2);
        l0 = l0 * al0 + rs0;
        l1 = l1 * al1 + rs1;
#pragma unroll
        for (int ot = 0; ot < 8; ot++) {
            o[ot][0] *= al0; o[ot][1] *= al0;
            o[ot][2] *= al1; o[ot][3] *= al1;
        }

        // ---- O += P . V  (P,V hi/lo; V via ldmatrix.trans) ----
#pragma unroll
        for (int k2 = 0; k2 < 4; k2++) {
            uint32_t ph[4], pl[4];
            pack_hilo(s[2 * k2][0],     s[2 * k2][1],     ph[0], pl[0]);
            pack_hilo(s[2 * k2][2],     s[2 * k2][3],     ph[1], pl[1]);
            pack_hilo(s[2 * k2 + 1][0], s[2 * k2 + 1][1], ph[2], pl[2]);
            pack_hilo(s[2 * k2 + 1][2], s[2 * k2 + 1][3], ph[3], pl[3]);
#pragma unroll
            for (int dt = 0; dt < 4; dt++) {
                uint32_t vo = swz128((uint32_t)((k2 * 16 + ar) * 128 + dt * 32 + ak2));
                uint32_t vh4[4], vl4[4];
                ldmat4t(vh4, kb + 16384 + vo);
                ldmat4t(vl4, kb + 24576 + vo);
                mma_bf16(o[2 * dt],     ph, vh4);
                mma_bf16(o[2 * dt + 1], ph, vh4 + 2);
                mma_bf16(o[2 * dt],     ph, vl4);
                mma_bf16(o[2 * dt + 1], ph, vl4 + 2);
                mma_bf16(o[2 * dt],     pl, vh4);
                mma_bf16(o[2 * dt + 1], pl, vh4 + 2);
            }
        }

        // ---- pipeline bookkeeping ----
        __syncthreads();                         // all warps done with stage kt&1
        if (kt + 2 < 16) { load_kv(kt & 1, kt + 2); CP_COMMIT(); }
        if (kt + 1 < 16) {
            if (kt + 2 < 16)
                asm volatile("cp.async.wait_group 1;" ::: "memory");
            else
                asm volatile("cp.async.wait_group 0;" ::: "memory");
            __syncthreads();
        }
    }

    // ---- epilogue: normalize, split to hi/lo bf16 ----
    float i0 = 1.f / l0, i1 = 1.f / l1;
    size_t ob0 = gb + (size_t)(q0 + wrow + r0) * DD;
    size_t ob1 = ob0 + 8 * DD;
#pragma unroll
    for (int dt = 0; dt < 8; dt++) {
        int dcol = dt * 8 + cq;
        uint32_t h0, lo0, h1, lo1;
        pack_hilo(o[dt][0] * i0, o[dt][1] * i0, h0, lo0);
        pack_hilo(o[dt][2] * i1, o[dt][3] * i1, h1, lo1);
        *reinterpret_cast<uint32_t*>(Ohi + ob0 + dcol) = h0;
        *reinterpret_cast<uint32_t*>(Olo + ob0 + dcol) = lo0;
        *reinterpret_cast<uint32_t*>(Ohi + ob1 + dcol) = h1;
        *reinterpret_cast<uint32_t*>(Olo + ob1 + dcol) = lo1;
    }
}

// ---------------- kernel 4: residual + LayerNorm -----------------------------
__global__ void __launch_bounds__(256) ln_kernel(
    const float* __restrict__ cur, const float* __restrict__ proj,
    const float* __restrict__ g, const float* __restrict__ bta,
    float* __restrict__ out)
{
    const int m = blockIdx.x;
    const int t = threadIdx.x;
    const float2 c2 = *reinterpret_cast<const float2*>(&cur[(size_t)m * DD + t * 2]);
    const float2 p2 = *reinterpret_cast<const float2*>(&proj[(size_t)m * DD + t * 2]);
    float x0 = c2.x + p2.x, x1 = c2.y + p2.y;
    float s = x0 + x1;
    float q = x0 * x0 + x1 * x1;
#pragma unroll
    for (int off = 16; off; off >>= 1) {
        s += __shfl_xor_sync(0xffffffffu, s, off);
        q += __shfl_xor_sync(0xffffffffu, q, off);
    }
    __shared__ float ss[8], qq[8];
    int w = t >> 5, lane = t & 31;
    if (lane == 0) { ss[w] = s; qq[w] = q; }
    __syncthreads();
    if (w == 0) {
        float s2 = (lane < 8) ? ss[lane] : 0.f;
        float q2 = (lane < 8) ? qq[lane] : 0.f;
#pragma unroll
        for (int off = 4; off; off >>= 1) {
            s2 += __shfl_xor_sync(0xffffffffu, s2, off);
            q2 += __shfl_xor_sync(0xffffffffu, q2, off);
        }
        if (lane == 0) { ss[0] = s2; qq[0] = q2; }
    }
    __syncthreads();
    const float mu  = ss[0] * (1.f / 512.f);
    const float var = qq[0] * (1.f / 512.f) - mu * mu;
    const float r   = rsqrtf(var + 1e-5f);
    const float2 g2 = *reinterpret_cast<const float2*>(&g[t * 2]);
    const float2 b2 = *reinterpret_cast<const float2*>(&bta[t * 2]);
    float2 o;
    o.x = (x0 - mu) * r * g2.x + b2.x;
    o.y = (x1 - mu) * r * g2.y + b2.y;
    *reinterpret_cast<float2*>(&out[(size_t)m * DD + t * 2]) = o;
}

// ---------------- launcher ---------------------------------------------------
extern "C" void kernel_launch(void* const* d_in, const int* in_sizes, int n_in,
                              void* d_out, int out_size)
{
    (void)in_sizes; (void)n_in; (void)out_size;
    const float* cur = (const float*)d_in[0];
    const float* lf  = (const float*)d_in[1];
    const float* lw  = (const float*)d_in[2];
    const float* Wq  = (const float*)d_in[3];
    const float* bq  = (const float*)d_in[4];
    const float* Wk  = (const float*)d_in[5];
    const float* bk  = (const float*)d_in[6];
    const float* Wv  = (const float*)d_in[7];
    const float* bv  = (const float*)d_in[8];
    const float* Wo  = (const float*)d_in[9];
    const float* bo  = (const float*)d_in[10];
    const float* adj = (const float*)d_in[11];
    const float* lng = (const float*)d_in[12];
    const float* lnb = (const float*)d_in[13];
    float* out = (float*)d_out;

    float* att;
    __nv_bfloat16 *ahi, *alo, *bhi, *blo, *whi, *wlo;
    __nv_bfloat16 *qhi, *qlo, *khi, *klo, *vhi, *vlo;
    cudaGetSymbolAddress((void**)&att, g_att);
    cudaGetSymbolAddress((void**)&ahi, g_ahi);
    cudaGetSymbolAddress((void**)&alo, g_alo);
    cudaGetSymbolAddress((void**)&bhi, g_bhi);
    cudaGetSymbolAddress((void**)&blo, g_blo);
    cudaGetSymbolAddress((void**)&whi, g_whi);
    cudaGetSymbolAddress((void**)&wlo, g_wlo);
    cudaGetSymbolAddress((void**)&qhi, g_qhi);
    cudaGetSymbolAddress((void**)&qlo, g_qlo);
    cudaGetSymbolAddress((void**)&khi, g_khi);
    cudaGetSymbolAddress((void**)&klo, g_klo);
    cudaGetSymbolAddress((void**)&vhi, g_vhi);
    cudaGetSymbolAddress((void**)&vlo, g_vlo);

    cudaFuncSetAttribute(gemm_mma_kernel,
                         cudaFuncAttributeMaxDynamicSharedMemorySize, GM_SMEM);
    cudaFuncSetAttribute(attn_mma_kernel,
                         cudaFuncAttributeMaxDynamicSharedMemorySize, AT_SMEM);

    const int WW = DD * DD;                  // 262144 elems per weight matrix
    dim3 ggrid(DD / 128, (BB * NN) / 128);   // (4, 128)

    // 1. input splits (weights once, current features)
    split_kernel<<<WW / 4 / 256, 256>>>(Wq, whi + 0 * WW, wlo + 0 * WW, WW / 4);
    split_kernel<<<WW / 4 / 256, 256>>>(Wk, whi + 1 * WW, wlo + 1 * WW, WW / 4);
    split_kernel<<<WW / 4 / 256, 256>>>(Wv, whi + 2 * WW, wlo + 2 * WW, WW / 4);
    split_kernel<<<WW / 4 / 256, 256>>>(Wo, whi + 3 * WW, wlo + 3 * WW, WW / 4);
    split_kernel<<<BND / 4 / 256, 256>>>(cur, ahi, alo, BND / 4);

    // 2. lag softmax + aggregation -> bf16 hi/lo directly
    lag_agg_kernel<<<BND / 4 / 256, 256>>>(lf, lw, bhi, blo);

    // 3. projections (Q pre-scaled by 1/sqrt(HD) = 0.125)
    gemm_mma_kernel<<<ggrid, 256, GM_SMEM>>>(ahi, alo, whi + 0 * WW, wlo + 0 * WW,
                                             bq, 0.125f, nullptr, qhi, qlo);
    gemm_mma_kernel<<<ggrid, 256, GM_SMEM>>>(bhi, blo, whi + 1 * WW, wlo + 1 * WW,
                                             bk, 1.0f, nullptr, khi, klo);
    gemm_mma_kernel<<<ggrid, 256, GM_SMEM>>>(bhi, blo, whi + 2 * WW, wlo + 2 * WW,
                                             bv, 1.0f, nullptr, vhi, vlo);

    // 4. attention (tensor cores) -> hi/lo split for O-projection
    attn_mma_kernel<<<dim3(NN / 128, BB * HH), 256, AT_SMEM>>>(
        qhi, qlo, khi, klo, vhi, vlo, adj, ahi, alo);

    // 5. output projection -> fp32
    gemm_mma_kernel<<<ggrid, 256, GM_SMEM>>>(ahi, alo, whi + 3 * WW, wlo + 3 * WW,
                                             bo, 1.0f, att, nullptr, nullptr);

    // 6. residual + layernorm
    ln_kernel<<<BB * NN, 256>>>(cur, att, lng, lnb, out);
}

// round 13
// speedup vs baseline: 2.7045x; 1.0183x over previous
#include <cuda_runtime.h>
#include <cuda_bf16.h>
#include <cstdint>

// ---------------- problem constants ----------------
#define BB 16
#define NN 1024
#define LL 7
#define DD 512
#define HH 8
#define HD 64
#define BND (BB * NN * DD)   // 8,388,608 elements

// ---------------- scratch (device globals; no allocations allowed) ----------
__device__ float g_att[BND];                                   // O-proj output (fp32)
__device__ __align__(16) __nv_bfloat16 g_ahi[BND], g_alo[BND]; // cur split / attn out
__device__ __align__(16) __nv_bfloat16 g_bhi[BND], g_blo[BND]; // lagged agg split
__device__ __align__(16) __nv_bfloat16 g_qhi[BND], g_qlo[BND];
__device__ __align__(16) __nv_bfloat16 g_khi[BND], g_klo[BND];
__device__ __align__(16) __nv_bfloat16 g_vhi[BND], g_vlo[BND];
__device__ __align__(16) __nv_bfloat16 g_whi[4 * DD * DD], g_wlo[4 * DD * DD];

// ---------------- helpers ----------------------------------------------------
__device__ __forceinline__ uint32_t smem_u32(const void* p) {
    uint32_t a;
    asm("{ .reg .u64 t; cvta.to.shared.u64 t, %1; cvt.u32.u64 %0, t; }"
        : "=r"(a) : "l"(p));
    return a;
}
__device__ __forceinline__ uint32_t swz128(uint32_t o) {
    return o ^ ((o >> 3) & 0x70);
}
// pack two fp32 into bf16x2: lo 16 bits = x, hi 16 bits = y
__device__ __forceinline__ uint32_t packbf(float x, float y) {
    uint32_t r;
    asm("cvt.rn.bf16x2.f32 %0, %1, %2;" : "=r"(r) : "f"(y), "f"(x));
    return r;
}
// hi/lo error-compensated bf16 split of a pair
__device__ __forceinline__ void pack_hilo(float x, float y, uint32_t& h, uint32_t& l) {
    h = packbf(x, y);
    float hx = __uint_as_float(h << 16);
    float hy = __uint_as_float(h & 0xFFFF0000u);
    l = packbf(x - hx, y - hy);
}
__device__ __forceinline__ void ldmat4(uint32_t* r, uint32_t addr) {
    asm volatile("ldmatrix.sync.aligned.m8n8.x4.shared.b16 {%0,%1,%2,%3}, [%4];"
                 : "=r"(r[0]), "=r"(r[1]), "=r"(r[2]), "=r"(r[3]) : "r"(addr));
}
__device__ __forceinline__ void ldmat4t(uint32_t* r, uint32_t addr) {
    asm volatile("ldmatrix.sync.aligned.m8n8.x4.trans.shared.b16 {%0,%1,%2,%3}, [%4];"
                 : "=r"(r[0]), "=r"(r[1]), "=r"(r[2]), "=r"(r[3]) : "r"(addr));
}
__device__ __forceinline__ void mma_bf16(float* d, const uint32_t* a,
                                         const uint32_t* b) {
    asm volatile("mma.sync.aligned.m16n8k16.row.col.f32.bf16.bf16.f32 "
                 "{%0,%1,%2,%3}, {%4,%5,%6,%7}, {%8,%9}, {%0,%1,%2,%3};"
                 : "+f"(d[0]), "+f"(d[1]), "+f"(d[2]), "+f"(d[3])
                 : "r"(a[0]), "r"(a[1]), "r"(a[2]), "r"(a[3]),
                   "r"(b[0]), "r"(b[1]));
}
__device__ __forceinline__ void cpa16(uint32_t s, const void* g) {
    asm volatile("cp.async.cg.shared.global [%0], [%1], 16;" :: "r"(s), "l"(g));
}
#define CP_COMMIT() asm volatile("cp.async.commit_group;" ::: "memory")

// ---------------- kernel 0a: fp32 -> bf16 hi/lo split ------------------------
__global__ void __launch_bounds__(256) split_kernel(
    const float* __restrict__ x, __nv_bfloat16* __restrict__ hi,
    __nv_bfloat16* __restrict__ lo, int n4)
{
    int i = blockIdx.x * 256 + threadIdx.x;
    if (i >= n4) return;
    float4 v = reinterpret_cast<const float4*>(x)[i];
    uint32_t h01, l01, h23, l23;
    pack_hilo(v.x, v.y, h01, l01);
    pack_hilo(v.z, v.w, h23, l23);
    reinterpret_cast<uint2*>(hi)[i] = make_uint2(h01, h23);
    reinterpret_cast<uint2*>(lo)[i] = make_uint2(l01, l23);
}

// ---------------- kernel 0b: all 4 weight splits in one launch ---------------
__global__ void __launch_bounds__(256) split4_kernel(
    const float* __restrict__ x0, const float* __restrict__ x1,
    const float* __restrict__ x2, const float* __restrict__ x3,
    __nv_bfloat16* __restrict__ hi, __nv_bfloat16* __restrict__ lo)
{
    const int WW4 = DD * DD / 4;
    const float* xs[4] = {x0, x1, x2, x3};
    const float* x = xs[blockIdx.y];
    int i = blockIdx.x * 256 + threadIdx.x;
    size_t o = (size_t)blockIdx.y * WW4 + i;
    float4 v = reinterpret_cast<const float4*>(x)[i];
    uint32_t h01, l01, h23, l23;
    pack_hilo(v.x, v.y, h01, l01);
    pack_hilo(v.z, v.w, h23, l23);
    reinterpret_cast<uint2*>(hi)[o] = make_uint2(h01, h23);
    reinterpret_cast<uint2*>(lo)[o] = make_uint2(l01, l23);
}

// ---------------- kernel 1: lag softmax + aggregation -> bf16 hi/lo ---------
__global__ void __launch_bounds__(256) lag_agg_kernel(
    const float* __restrict__ lf, const float* __restrict__ lw,
    __nv_bfloat16* __restrict__ hi, __nv_bfloat16* __restrict__ lo)
{
    int idx = blockIdx.x * 256 + threadIdx.x;          // one float4 per thread
    float w[LL]; float mx = -1e30f, sum = 0.f;
#pragma unroll
    for (int l = 0; l < LL; l++) { w[l] = __ldg(&lw[l]); mx = fmaxf(mx, w[l]); }
#pragma unroll
    for (int l = 0; l < LL; l++) { w[l] = __expf(w[l] - mx); sum += w[l]; }
    float inv = 1.f / sum;

    int row = idx >> 7;                 // (b*N + n), 128 float4 per row
    int c4  = (idx & 127) << 2;
    size_t base = (size_t)row * LL * DD + c4;
    float ax = 0.f, ay = 0.f, az = 0.f, aw = 0.f;
#pragma unroll
    for (int l = 0; l < LL; l++) {
        float4 v = *reinterpret_cast<const float4*>(&lf[base + (size_t)l * DD]);
        float wl = w[l] * inv;
        ax += wl * v.x; ay += wl * v.y; az += wl * v.z; aw += wl * v.w;
    }
    uint32_t h01, l01, h23, l23;
    pack_hilo(ax, ay, h01, l01);
    pack_hilo(az, aw, h23, l23);
    reinterpret_cast<uint2*>(hi)[idx] = make_uint2(h01, h23);
    reinterpret_cast<uint2*>(lo)[idx] = make_uint2(l01, l23);
}

// ============================================================================
// kernel 2: bf16x3 GEMM, 4 warps (2Mx2N), warp tile 64x64, K-chunk 32,
// 3-stage cp.async pipeline, 128 threads, 2 CTAs/SM.
// Stage (32KB): A 16KB | B 16KB; each row 128B = [hi 32bf16 | lo 32bf16]
// ============================================================================
#define GKC  32
#define GSTG 32768
#define GM_SMEM (3 * GSTG)

__global__ void __launch_bounds__(128, 2) gemm_mma_kernel(
    const __nv_bfloat16* __restrict__ Ahi, const __nv_bfloat16* __restrict__ Alo,
    const __nv_bfloat16* __restrict__ Whi, const __nv_bfloat16* __restrict__ Wlo,
    const float* __restrict__ bias, float scale,
    float* __restrict__ C,
    __nv_bfloat16* __restrict__ Chi, __nv_bfloat16* __restrict__ Clo)
{
    extern __shared__ __align__(1024) char smem[];
    const int t    = threadIdx.x;        // 0..127
    const int wid  = t >> 5;             // 0..3
    const int lane = t & 31;
    const int bm   = blockIdx.y * 128;
    const int bn   = blockIdx.x * 128;
    const int wm   = (wid >> 1) * 64;    // warp M offset (0/64)
    const int wn   = (wid & 1) * 64;     // warp N offset (0/64)
    const uint32_t sbase = smem_u32(smem);

    float acc[4][8][4];                  // mt(4 x m16) x n8(8) x 4
#pragma unroll
    for (int i = 0; i < 4; i++)
#pragma unroll
        for (int j = 0; j < 8; j++)
#pragma unroll
            for (int k = 0; k < 4; k++) acc[i][j][k] = 0.f;

    // per-stage: 1024 slots per matrix = 128 rows x 8 x 16B (4 hi + 4 lo)
    auto load_chunk = [&](int s, int c) {
        const uint32_t base = sbase + (uint32_t)s * GSTG;
        const int kb = c * GKC;
#pragma unroll
        for (int i = 0; i < 8; i++) {
            int slot = t + i * 128;
            int row = slot >> 3, j = slot & 7;
            uint32_t dst = swz128((uint32_t)(row * 128 + j * 16));
            const __nv_bfloat16* a = (j < 4) ? Ahi : Alo;
            const __nv_bfloat16* w = (j < 4) ? Whi : Wlo;
            int jc = (j & 3) * 8;
            cpa16(base + dst,         a + (size_t)(bm + row) * DD + kb + jc);
            cpa16(base + 16384 + dst, w + (size_t)(bn + row) * DD + kb + jc);
        }
    };

    load_chunk(0, 0); CP_COMMIT();
    load_chunk(1, 1); CP_COMMIT();
    load_chunk(2, 2); CP_COMMIT();

    const int ar  = lane & 15;
    const int ak2 = (lane >> 4) * 16;               // byte offset of k-half
    const int br  = (lane & 7) + ((lane >> 4) << 3);
    const int bk2 = ((lane >> 3) & 1) * 16;

    for (int c = 0; c < 16; c++) {
        if (c < 14)       asm volatile("cp.async.wait_group 2;" ::: "memory");
        else if (c == 14) asm volatile("cp.async.wait_group 1;" ::: "memory");
        else              asm volatile("cp.async.wait_group 0;" ::: "memory");
        __syncthreads();

        const uint32_t base = sbase + (uint32_t)((c % 3) * GSTG);
#pragma unroll
        for (int ks = 0; ks < 2; ks++) {
            uint32_t ah[4][4], al[4][4];
#pragma unroll
            for (int mt = 0; mt < 4; mt++) {
                uint32_t ro = (uint32_t)((wm + mt * 16 + ar) * 128 + ks * 32 + ak2);
                ldmat4(ah[mt], base + swz128(ro));
                ldmat4(al[mt], base + swz128(ro + 64));
            }
#pragma unroll
            for (int np = 0; np < 4; np++) {
                uint32_t ro = (uint32_t)((wn + np * 16 + br) * 128 + ks * 32 + bk2);
                uint32_t bh[4], bl[4];
                ldmat4(bh, base + 16384 + swz128(ro));
                ldmat4(bl, base + 16384 + swz128(ro + 64));
#pragma unroll
                for (int mt = 0; mt < 4; mt++) {
                    mma_bf16(acc[mt][2 * np],     ah[mt], bh);
                    mma_bf16(acc[mt][2 * np + 1], ah[mt], bh + 2);
                    mma_bf16(acc[mt][2 * np],     ah[mt], bl);
                    mma_bf16(acc[mt][2 * np + 1], ah[mt], bl + 2);
                    mma_bf16(acc[mt][2 * np],     al[mt], bh);
                    mma_bf16(acc[mt][2 * np + 1], al[mt], bh + 2);
                }
            }
        }
        __syncthreads();
        if (c + 3 < 16) { load_chunk(c % 3, c + 3); CP_COMMIT(); }
    }

    // ---- epilogue ----
    const int r0 = lane >> 2;
    const int c0 = (lane & 3) * 2;
#pragma unroll
    for (int mt = 0; mt < 4; mt++) {
#pragma unroll
        for (int nt = 0; nt < 8; nt++) {
            int gn = bn + wn + nt * 8 + c0;
            float2 bv = *reinterpret_cast<const float2*>(bias + gn);
            int gm = bm + wm + mt * 16 + r0;
            float v0 = (acc[mt][nt][0] + bv.x) * scale;
            float v1 = (acc[mt][nt][1] + bv.y) * scale;
            float v2 = (acc[mt][nt][2] + bv.x) * scale;
            float v3 = (acc[mt][nt][3] + bv.y) * scale;
            size_t o0 = (size_t)gm * DD + gn;
            size_t o1 = (size_t)(gm + 8) * DD + gn;
            if (Chi) {
                uint32_t h, l;
                pack_hilo(v0, v1, h, l);
                *reinterpret_cast<uint32_t*>(Chi + o0) = h;
                *reinterpret_cast<uint32_t*>(Clo + o0) = l;
                pack_hilo(v2, v3, h, l);
                *reinterpret_cast<uint32_t*>(Chi + o1) = h;
                *reinterpret_cast<uint32_t*>(Clo + o1) = l;
            } else {
                *reinterpret_cast<float2*>(C + o0) = make_float2(v0, v1);
                *reinterpret_cast<float2*>(C + o1) = make_float2(v2, v3);
            }
        }
    }
}

// ============================================================================
// kernel 3: flash attention, 4 warps x m32 query rows, 128 threads, 2 CTAs/SM
//   16 key tiles of 64, cp.async double-buffered K/V (hi/lo).
//   Q-hi fragments register-resident; Q-lo reloaded per k-step.
//   V fragments shared across both m16 halves of the warp tile.
// smem: Qh 16K | Ql 16K | stage{0,1} x {Kh 8K | Kl 8K | Vh 8K | Vl 8K} = 96K
// ============================================================================
#define AT_SMEM (32768 + 2 * 32768)

__global__ void __launch_bounds__(128, 2) attn_mma_kernel(
    const __nv_bfloat16* __restrict__ Qh_, const __nv_bfloat16* __restrict__ Ql_,
    const __nv_bfloat16* __restrict__ Kh_, const __nv_bfloat16* __restrict__ Kl_,
    const __nv_bfloat16* __restrict__ Vh_, const __nv_bfloat16* __restrict__ Vl_,
    const float* __restrict__ adj,
    __nv_bfloat16* __restrict__ Ohi, __nv_bfloat16* __restrict__ Olo)
{
    extern __shared__ __align__(1024) char smem[];
    const int t    = threadIdx.x;       // 0..127
    const int wid  = t >> 5;            // 0..3
    const int lane = t & 31;
    const int b    = blockIdx.y >> 3;
    const int h    = blockIdx.y & 7;
    const int q0   = blockIdx.x * 128;
    const uint32_t sb = smem_u32(smem);
    const size_t gb = (size_t)b * NN * DD + h * HD;

    // ---- Q tiles via cp.async ----
#pragma unroll
    for (int i = 0; i < 8; i++) {
        int s2 = t + i * 128;          // 1024 slots = 128 rows x 8 col-groups
        int row = s2 >> 3, c8 = s2 & 7;
        uint32_t so = swz128((uint32_t)(row * 128 + c8 * 16));
        size_t g = gb + (size_t)(q0 + row) * DD + c8 * 8;
        cpa16(sb + so,         Qh_ + g);
        cpa16(sb + 16384 + so, Ql_ + g);
    }
    auto load_kv = [&](int stg, int kt) {
        uint32_t base = sb + 32768 + (uint32_t)stg * 32768;
#pragma unroll
        for (int i = 0; i < 4; i++) {
            int s2 = t + i * 128;      // 512 slots = 64 rows x 8 col-groups
            int row = s2 >> 3, c8 = s2 & 7;
            uint32_t so = swz128((uint32_t)(row * 128 + c8 * 16));
            size_t g = gb + (size_t)(kt * 64 + row) * DD + c8 * 8;
            cpa16(base + so,         Kh_ + g);
            cpa16(base + 8192 + so,  Kl_ + g);
            cpa16(base + 16384 + so, Vh_ + g);
            cpa16(base + 24576 + so, Vl_ + g);
        }
    };
    load_kv(0, 0); CP_COMMIT();
    load_kv(1, 1); CP_COMMIT();
    asm volatile("cp.async.wait_group 1;" ::: "memory");
    __syncthreads();

    // ---- Q-hi A-fragments (resident); Q-lo reloaded on demand ----
    const int ar   = lane & 15;
    const int ak2  = (lane >> 4) * 16;          // byte offset of k-half
    const int wrow = wid * 32;                  // warp owns rows wrow..wrow+31
    uint32_t qh[2][4][4], qao[2][4];
#pragma unroll
    for (int mt = 0; mt < 2; mt++)
#pragma unroll
        for (int ks = 0; ks < 4; ks++) {
            qao[mt][ks] = sb + swz128(
                (uint32_t)((wrow + mt * 16 + ar) * 128 + ks * 32 + ak2));
            ldmat4(qh[mt][ks], qao[mt][ks]);
        }

    float o[2][8][4];
#pragma unroll
    for (int mt = 0; mt < 2; mt++)
#pragma unroll
        for (int i = 0; i < 8; i++)
#pragma unroll
            for (int j = 0; j < 4; j++) o[mt][i][j] = 0.f;
    float mrow[2][2], lrow[2][2];
#pragma unroll
    for (int mt = 0; mt < 2; mt++) {
        mrow[mt][0] = -1e30f; mrow[mt][1] = -1e30f;
        lrow[mt][0] = 0.f;    lrow[mt][1] = 0.f;
    }

    const int r0 = lane >> 2;
    const int cq = (lane & 3) * 2;
    const float* arp[2][2];
#pragma unroll
    for (int mt = 0; mt < 2; mt++) {
        arp[mt][0] = adj + (size_t)(q0 + wrow + mt * 16 + r0) * NN + cq;
        arp[mt][1] = arp[mt][0] + 8 * NN;
    }

    const int br  = (lane & 7) + ((lane >> 4) << 3);
    const int bk2 = ((lane >> 3) & 1) * 16;    // byte offset

    for (int kt = 0; kt < 16; kt++) {
        const uint32_t kb = sb + 32768 + (uint32_t)(kt & 1) * 32768;

        // ---- S = Q . K^T  (32 rows x 64 keys), bf16x3 ----
        float s[2][8][4];
#pragma unroll
        for (int mt = 0; mt < 2; mt++)
#pragma unroll
            for (int i = 0; i < 8; i++)
#pragma unroll
                for (int j = 0; j < 4; j++) s[mt][i][j] = 0.f;
#pragma unroll
        for (int ks = 0; ks < 4; ks++) {
            uint32_t qlk[2][4];
            ldmat4(qlk[0], qao[0][ks] + 16384);
            ldmat4(qlk[1], qao[1][ks] + 16384);
#pragma unroll
            for (int ng = 0; ng < 4; ng++) {
                uint32_t bo = swz128((uint32_t)((ng * 16 + br) * 128 + ks * 32 + bk2));
                uint32_t bh4[4], bl4[4];
                ldmat4(bh4, kb + bo);
                ldmat4(bl4, kb + 8192 + bo);
#pragma unroll
                for (int mt = 0; mt < 2; mt++) {
                    mma_bf16(s[mt][2 * ng],     qh[mt][ks], bh4);
                    mma_bf16(s[mt][2 * ng + 1], qh[mt][ks], bh4 + 2);
                    mma_bf16(s[mt][2 * ng],     qh[mt][ks], bl4);
                    mma_bf16(s[mt][2 * ng + 1], qh[mt][ks], bl4 + 2);
                    mma_bf16(s[mt][2 * ng],     qlk[mt], bh4);
                    mma_bf16(s[mt][2 * ng + 1], qlk[mt], bh4 + 2);
                }
            }
        }

        // ---- + 0.5 * adj; online softmax per mt ----
#pragma unroll
        for (int mt = 0; mt < 2; mt++) {
#pragma unroll
            for (int nt = 0; nt < 8; nt++) {
                int c = kt * 64 + nt * 8;
                float2 a0 = *reinterpret_cast<const float2*>(arp[mt][0] + c);
                float2 a1 = *reinterpret_cast<const float2*>(arp[mt][1] + c);
                s[mt][nt][0] += 0.5f * a0.x; s[mt][nt][1] += 0.5f * a0.y;
                s[mt][nt][2] += 0.5f * a1.x; s[mt][nt][3] += 0.5f * a1.y;
            }
            float tm0 = -1e30f, tm1 = -1e30f;
#pragma unroll
            for (int nt = 0; nt < 8; nt++) {
                tm0 = fmaxf(tm0, fmaxf(s[mt][nt][0], s[mt][nt][1]));
                tm1 = fmaxf(tm1, fmaxf(s[mt][nt][2], s[mt][nt][3]));
            }
            tm0 = fmaxf(tm0, __shfl_xor_sync(0xffffffffu, tm0, 1));
            tm0 = fmaxf(tm0, __shfl_xor_sync(0xffffffffu, tm0, 2));
            tm1 = fmaxf(tm1, __shfl_xor_sync(0xffffffffu, tm1, 1));
            tm1 = fmaxf(tm1, __shfl_xor_sync(0xffffffffu, tm1, 2));
            float mn0 = fmaxf(mrow[mt][0], tm0), mn1 = fmaxf(mrow[mt][1], tm1);
            float al0 = __expf(mrow[mt][0] - mn0), al1 = __expf(mrow[mt][1] - mn1);
            mrow[mt][0] = mn0; mrow[mt][1] = mn1;
            float rs0 = 0.f, rs1 = 0.f;
#pragma unroll
            for (int nt = 0; nt < 8; nt++) {
                s[mt][nt][0] = __expf(s[mt][nt][0] - mn0);
                s[mt][nt][1] = __expf(s[mt][nt][1] - mn0);
                s[mt][nt][2] = __expf(s[mt][nt][2] - mn1);
                s[mt][nt][3] = __expf(s[mt][nt][3] - mn1);
                rs0 += s[mt][nt][0] + s[mt][nt][1];
                rs1 += s[mt][nt][2] + s[mt][nt][3];
            }
            rs0 += __shfl_xor_sync(0xffffffffu, rs0, 1);
            rs0 += __shfl_xor_sync(0xffffffffu, rs0, 2);
            rs1 += __shfl_xor_sync(0xffffffffu, rs1, 1);
            rs1 += __shfl_xor_sync(0xffffffffu, rs1, 2);
            lrow[mt][0] = lrow[mt][0] * al0 + rs0;
            lrow[mt][1] = lrow[mt][1] * al1 + rs1;
#pragma unroll
            for (int ot = 0; ot < 8; ot++) {
                o[mt][ot][0] *= al0; o[mt][ot][1] *= al0;
                o[mt][ot][2] *= al1; o[mt][ot][3] *= al1;
            }
        }

        // ---- O += P . V  (P,V hi/lo; V via ldmatrix.trans, shared by mt) ----
#pragma unroll
        for (int k2 = 0; k2 < 4; k2++) {
            uint32_t ph[2][4], pl[2][4];
#pragma unroll
            for (int mt = 0; mt < 2; mt++) {
                pack_hilo(s[mt][2 * k2][0],     s[mt][2 * k2][1],     ph[mt][0], pl[mt][0]);
                pack_hilo(s[mt][2 * k2][2],     s[mt][2 * k2][3],     ph[mt][1], pl[mt][1]);
                pack_hilo(s[mt][2 * k2 + 1][0], s[mt][2 * k2 + 1][1], ph[mt][2], pl[mt][2]);
                pack_hilo(s[mt][2 * k2 + 1][2], s[mt][2 * k2 + 1][3], ph[mt][3], pl[mt][3]);
            }
#pragma unroll
            for (int dt = 0; dt < 4; dt++) {
                uint32_t vo = swz128((uint32_t)((k2 * 16 + ar) * 128 + dt * 32 + ak2));
                uint32_t vh4[4], vl4[4];
                ldmat4t(vh4, kb + 16384 + vo);
                ldmat4t(vl4, kb + 24576 + vo);
#pragma unroll
                for (int mt = 0; mt < 2; mt++) {
                    mma_bf16(o[mt][2 * dt],     ph[mt], vh4);
                    mma_bf16(o[mt][2 * dt + 1], ph[mt], vh4 + 2);
                    mma_bf16(o[mt][2 * dt],     ph[mt], vl4);
                    mma_bf16(o[mt][2 * dt + 1], ph[mt], vl4 + 2);
                    mma_bf16(o[mt][2 * dt],     pl[mt], vh4);
                    mma_bf16(o[mt][2 * dt + 1], pl[mt], vh4 + 2);
                }
            }
        }

        // ---- pipeline bookkeeping ----
        __syncthreads();                         // all warps done with stage kt&1
        if (kt + 2 < 16) { load_kv(kt & 1, kt + 2); CP_COMMIT(); }
        if (kt + 1 < 16) {
            if (kt + 2 < 16)
                asm volatile("cp.async.wait_group 1;" ::: "memory");
            else
                asm volatile("cp.async.wait_group 0;" ::: "memory");
            __syncthreads();
        }
    }

    // ---- epilogue: normalize, split to hi/lo bf16 ----
#pragma unroll
    for (int mt = 0; mt < 2; mt++) {
        float i0 = 1.f / lrow[mt][0], i1 = 1.f / lrow[mt][1];
        size_t ob0 = gb + (size_t)(q0 + wrow + mt * 16 + r0) * DD;
        size_t ob1 = ob0 + 8 * DD;
#pragma unroll
        for (int dt = 0; dt < 8; dt++) {
            int dcol = dt * 8 + cq;
            uint32_t h0, lo0, h1, lo1;
            pack_hilo(o[mt][dt][0] * i0, o[mt][dt][1] * i0, h0, lo0);
            pack_hilo(o[mt][dt][2] * i1, o[mt][dt][3] * i1, h1, lo1);
            *reinterpret_cast<uint32_t*>(Ohi + ob0 + dcol) = h0;
            *reinterpret_cast<uint32_t*>(Olo + ob0 + dcol) = lo0;
            *reinterpret_cast<uint32_t*>(Ohi + ob1 + dcol) = h1;
            *reinterpret_cast<uint32_t*>(Olo + ob1 + dcol) = lo1;
        }
    }
}

// ---------------- kernel 4: residual + LayerNorm -----------------------------
__global__ void __launch_bounds__(256) ln_kernel(
    const float* __restrict__ cur, const float* __restrict__ proj,
    const float* __restrict__ g, const float* __restrict__ bta,
    float* __restrict__ out)
{
    const int m = blockIdx.x;
    const int t = threadIdx.x;
    const float2 c2 = *reinterpret_cast<const float2*>(&cur[(size_t)m * DD + t * 2]);
    const float2 p2 = *reinterpret_cast<const float2*>(&proj[(size_t)m * DD + t * 2]);
    float x0 = c2.x + p2.x, x1 = c2.y + p2.y;
    float s = x0 + x1;
    float q = x0 * x0 + x1 * x1;
#pragma unroll
    for (int off = 16; off; off >>= 1) {
        s += __shfl_xor_sync(0xffffffffu, s, off);
        q += __shfl_xor_sync(0xffffffffu, q, off);
    }
    __shared__ float ss[8], qq[8];
    int w = t >> 5, lane = t & 31;
    if (lane == 0) { ss[w] = s; qq[w] = q; }
    __syncthreads();
    if (w == 0) {
        float s2 = (lane < 8) ? ss[lane] : 0.f;
        float q2 = (lane < 8) ? qq[lane] : 0.f;
#pragma unroll
        for (int off = 4; off; off >>= 1) {
            s2 += __shfl_xor_sync(0xffffffffu, s2, off);
            q2 += __shfl_xor_sync(0xffffffffu, q2, off);
        }
        if (lane == 0) { ss[0] = s2; qq[0] = q2; }
    }
    __syncthreads();
    const float mu  = ss[0] * (1.f / 512.f);
    const float var = qq[0] * (1.f / 512.f) - mu * mu;
    const float r   = rsqrtf(var + 1e-5f);
    const float2 g2 = *reinterpret_cast<const float2*>(&g[t * 2]);
    const float2 b2 = *reinterpret_cast<const float2*>(&bta[t * 2]);
    float2 o;
    o.x = (x0 - mu) * r * g2.x + b2.x;
    o.y = (x1 - mu) * r * g2.y + b2.y;
    *reinterpret_cast<float2*>(&out[(size_t)m * DD + t * 2]) = o;
}

// ---------------- launcher ---------------------------------------------------
extern "C" void kernel_launch(void* const* d_in, const int* in_sizes, int n_in,
                              void* d_out, int out_size)
{
    (void)in_sizes; (void)n_in; (void)out_size;
    const float* cur = (const float*)d_in[0];
    const float* lf  = (const float*)d_in[1];
    const float* lw  = (const float*)d_in[2];
    const float* Wq  = (const float*)d_in[3];
    const float* bq  = (const float*)d_in[4];
    const float* Wk  = (const float*)d_in[5];
    const float* bk  = (const float*)d_in[6];
    const float* Wv  = (const float*)d_in[7];
    const float* bv  = (const float*)d_in[8];
    const float* Wo  = (const float*)d_in[9];
    const float* bo  = (const float*)d_in[10];
    const float* adj = (const float*)d_in[11];
    const float* lng = (const float*)d_in[12];
    const float* lnb = (const float*)d_in[13];
    float* out = (float*)d_out;

    float* att;
    __nv_bfloat16 *ahi, *alo, *bhi, *blo, *whi, *wlo;
    __nv_bfloat16 *qhi, *qlo, *khi, *klo, *vhi, *vlo;
    cudaGetSymbolAddress((void**)&att, g_att);
    cudaGetSymbolAddress((void**)&ahi, g_ahi);
    cudaGetSymbolAddress((void**)&alo, g_alo);
    cudaGetSymbolAddress((void**)&bhi, g_bhi);
    cudaGetSymbolAddress((void**)&blo, g_blo);
    cudaGetSymbolAddress((void**)&whi, g_whi);
    cudaGetSymbolAddress((void**)&wlo, g_wlo);
    cudaGetSymbolAddress((void**)&qhi, g_qhi);
    cudaGetSymbolAddress((void**)&qlo, g_qlo);
    cudaGetSymbolAddress((void**)&khi, g_khi);
    cudaGetSymbolAddress((void**)&klo, g_klo);
    cudaGetSymbolAddress((void**)&vhi, g_vhi);
    cudaGetSymbolAddress((void**)&vlo, g_vlo);

    cudaFuncSetAttribute(gemm_mma_kernel,
                         cudaFuncAttributeMaxDynamicSharedMemorySize, GM_SMEM);
    cudaFuncSetAttribute(attn_mma_kernel,
                         cudaFuncAttributeMaxDynamicSharedMemorySize, AT_SMEM);

    const int WW = DD * DD;                  // 262144 elems per weight matrix
    dim3 ggrid(DD / 128, (BB * NN) / 128);   // (4, 128)

    // 1. input splits: 4 weights in one launch + current features
    split4_kernel<<<dim3(WW / 4 / 256, 4), 256>>>(Wq, Wk, Wv, Wo, whi, wlo);
    split_kernel<<<BND / 4 / 256, 256>>>(cur, ahi, alo, BND / 4);

    // 2. lag softmax + aggregation -> bf16 hi/lo directly
    lag_agg_kernel<<<BND / 4 / 256, 256>>>(lf, lw, bhi, blo);

    // 3. projections (Q pre-scaled by 1/sqrt(HD) = 0.125)
    gemm_mma_kernel<<<ggrid, 128, GM_SMEM>>>(ahi, alo, whi + 0 * WW, wlo + 0 * WW,
                                             bq, 0.125f, nullptr, qhi, qlo);
    gemm_mma_kernel<<<ggrid, 128, GM_SMEM>>>(bhi, blo, whi + 1 * WW, wlo + 1 * WW,
                                             bk, 1.0f, nullptr, khi, klo);
    gemm_mma_kernel<<<ggrid, 128, GM_SMEM>>>(bhi, blo, whi + 2 * WW, wlo + 2 * WW,
                                             bv, 1.0f, nullptr, vhi, vlo);

    // 4. attention (tensor cores) -> hi/lo split for O-projection
    attn_mma_kernel<<<dim3(NN / 128, BB * HH), 128, AT_SMEM>>>(
        qhi, qlo, khi, klo, vhi, vlo, adj, ahi, alo);

    // 5. output projection -> fp32
    gemm_mma_kernel<<<ggrid, 128, GM_SMEM>>>(ahi, alo, whi + 3 * WW, wlo + 3 * WW,
                                             bo, 1.0f, att, nullptr, nullptr);

    // 6. residual + layernorm
    ln_kernel<<<BB * NN, 256>>>(cur, att, lng, lnb, out);
}